// round 7
// baseline (speedup 1.0000x reference)
#include <cuda_runtime.h>
#include <cuda_bf16.h>
#include <math.h>
#include <stdint.h>

#define EMB   768
#define NHEAD 12
#define HDIM  64
#define SEQ   1024
#define BATCH 8
#define MTOT  (BATCH * SEQ)
#define FQKV  (3 * EMB)
#define BHTOT (BATCH * NHEAD)

__device__ float g_qkv[(size_t)MTOT * FQKV];   // 75.5 MB
__device__ float g_oh [(size_t)MTOT * EMB];    // 25.2 MB
__device__ __nv_bfloat16 g_xh[(size_t)MTOT * EMB];
__device__ __nv_bfloat16 g_xl[(size_t)MTOT * EMB];
__device__ __nv_bfloat16 g_wh[(size_t)FQKV * EMB];
__device__ __nv_bfloat16 g_wl[(size_t)FQKV * EMB];

__device__ __forceinline__ uint32_t f2tf(float x) {
    uint32_t r;
    asm("cvt.rna.tf32.f32 %0, %1;" : "=r"(r) : "f"(x));
    return r;
}

__device__ __forceinline__ uint32_t smaddr(const void* p) {
    return (uint32_t)__cvta_generic_to_shared(p);
}

__device__ __forceinline__ void ldsm4(uint32_t* r, uint32_t a) {
    asm volatile("ldmatrix.sync.aligned.m8n8.x4.shared.b16 {%0,%1,%2,%3}, [%4];"
                 : "=r"(r[0]), "=r"(r[1]), "=r"(r[2]), "=r"(r[3]) : "r"(a));
}

__device__ __forceinline__ void cp16(uint32_t dst, const void* src) {
    asm volatile("cp.async.cg.shared.global [%0], [%1], 16;" :: "r"(dst), "l"(src));
}

__device__ __forceinline__ void mma8(float* c,
                                     uint32_t a0, uint32_t a1, uint32_t a2, uint32_t a3,
                                     uint32_t b0, uint32_t b1)
{
    asm volatile(
        "mma.sync.aligned.m16n8k8.row.col.f32.tf32.tf32.f32 "
        "{%0,%1,%2,%3}, {%4,%5,%6,%7}, {%8,%9}, {%0,%1,%2,%3};\n"
        : "+f"(c[0]), "+f"(c[1]), "+f"(c[2]), "+f"(c[3])
        : "r"(a0), "r"(a1), "r"(a2), "r"(a3), "r"(b0), "r"(b1));
}

__device__ __forceinline__ void mma16(float* c, const uint32_t* a,
                                      uint32_t b0, uint32_t b1)
{
    asm volatile(
        "mma.sync.aligned.m16n8k16.row.col.f32.bf16.bf16.f32 "
        "{%0,%1,%2,%3}, {%4,%5,%6,%7}, {%8,%9}, {%0,%1,%2,%3};\n"
        : "+f"(c[0]), "+f"(c[1]), "+f"(c[2]), "+f"(c[3])
        : "r"(a[0]), "r"(a[1]), "r"(a[2]), "r"(a[3]), "r"(b0), "r"(b1));
}

// ===========================================================================
// Pre-split: fp32 -> bf16 hi + bf16 lo (residual). Memory-bound, one pass.
// ===========================================================================
__global__ void __launch_bounds__(256) k_split(const float* __restrict__ src,
                                               __nv_bfloat16* __restrict__ hi,
                                               __nv_bfloat16* __restrict__ lo,
                                               int n4)
{
    int i = blockIdx.x * blockDim.x + threadIdx.x;
    if (i >= n4) return;
    float4 v = reinterpret_cast<const float4*>(src)[i];
    __nv_bfloat162 h0 = __floats2bfloat162_rn(v.x, v.y);
    __nv_bfloat162 h1 = __floats2bfloat162_rn(v.z, v.w);
    __nv_bfloat162 l0 = __floats2bfloat162_rn(v.x - __bfloat162float(h0.x),
                                              v.y - __bfloat162float(h0.y));
    __nv_bfloat162 l1 = __floats2bfloat162_rn(v.z - __bfloat162float(h1.x),
                                              v.w - __bfloat162float(h1.y));
    reinterpret_cast<__nv_bfloat162*>(hi)[i * 2]     = h0;
    reinterpret_cast<__nv_bfloat162*>(hi)[i * 2 + 1] = h1;
    reinterpret_cast<__nv_bfloat162*>(lo)[i * 2]     = l0;
    reinterpret_cast<__nv_bfloat162*>(lo)[i * 2 + 1] = l1;
}

// ===========================================================================
// QKV projection: pre-split bf16 inputs, cp.async double-buffered,
// block 128x64, 3x mma16 per k16. 3 CTAs/SM target.
// ===========================================================================
#define PSTR 20                         // 16 words (32 bf16) + 4 pad
#define QKV_STAGE (128*PSTR + 128*PSTR + 64*PSTR + 64*PSTR)   // 7680 words

__device__ __forceinline__ void qkv_issue(uint32_t base, int row0, int col0,
                                          int k0, int t)
{
    #pragma unroll
    for (int i = 0; i < 2; i++) {
        int idx = t + i * 256;
        int r = idx >> 2, seg = idx & 3;
        uint32_t dst = base + (uint32_t)(r * PSTR + seg * 4) * 4;
        size_t so = (size_t)(row0 + r) * EMB + k0 + seg * 8;
        cp16(dst,                    g_xh + so);
        cp16(dst + 128 * PSTR * 4,   g_xl + so);
    }
    {
        int r = t >> 2, seg = t & 3;
        uint32_t dst = base + (uint32_t)(256 * PSTR + r * PSTR + seg * 4) * 4;
        size_t so = (size_t)(col0 + r) * EMB + k0 + seg * 8;
        cp16(dst,                    g_wh + so);
        cp16(dst + 64 * PSTR * 4,    g_wl + so);
    }
    asm volatile("cp.async.commit_group;" ::: "memory");
}

__global__ void __launch_bounds__(256, 3) k_qkv(const float* __restrict__ bias)
{
    extern __shared__ uint32_t smu[];

    const int row0 = blockIdx.y * 128, col0 = blockIdx.x * 64;
    const int t = threadIdx.x, warp = t >> 5, lane = t & 31;
    const int wm = warp >> 2, wn = warp & 3;
    const int g = lane >> 2, tg = lane & 3;
    const int lr = lane & 15, lc = (lane >> 4) << 2;

    const uint32_t sbase = smaddr(smu);
    float acc[4][2][4] = {};

    qkv_issue(sbase, row0, col0, 0, t);

    for (int s = 0; s < 24; s++) {
        if (s < 23) {
            qkv_issue(sbase + ((s + 1) & 1) * (QKV_STAGE * 4), row0, col0,
                      (s + 1) * 32, t);
            asm volatile("cp.async.wait_group 1;" ::: "memory");
        } else {
            asm volatile("cp.async.wait_group 0;" ::: "memory");
        }
        __syncthreads();

        const uint32_t sb  = sbase + (s & 1) * (QKV_STAGE * 4);
        const uint32_t aAh = sb + (uint32_t)((wm * 64 + lr) * PSTR + lc) * 4;
        const uint32_t aAl = aAh + 128 * PSTR * 4;
        const uint32_t aBh = sb + (uint32_t)(256 * PSTR + (wn * 16 + lr) * PSTR + lc) * 4;
        const uint32_t aBl = aBh + 64 * PSTR * 4;

        #pragma unroll
        for (int ks = 0; ks < 2; ks++) {
            const uint32_t po = (uint32_t)(ks * 8) * 4;
            uint32_t bh[4], bl[4];
            ldsm4(bh, aBh + po);
            ldsm4(bl, aBl + po);
            #pragma unroll
            for (int mi = 0; mi < 4; mi++) {
                uint32_t ah[4], al[4];
                ldsm4(ah, aAh + (uint32_t)(mi * 16 * PSTR) * 4 + po);
                ldsm4(al, aAl + (uint32_t)(mi * 16 * PSTR) * 4 + po);
                #pragma unroll
                for (int ni = 0; ni < 2; ni++) {
                    float* c = acc[mi][ni];
                    mma16(c, ah, bh[ni], bh[2 + ni]);
                    mma16(c, ah, bl[ni], bl[2 + ni]);
                    mma16(c, al, bh[ni], bh[2 + ni]);
                }
            }
        }
        __syncthreads();
    }

    #pragma unroll
    for (int mi = 0; mi < 4; mi++) {
        int r0 = row0 + wm * 64 + mi * 16 + g;
        #pragma unroll
        for (int ni = 0; ni < 2; ni++) {
            int c = col0 + wn * 16 + ni * 8 + 2 * tg;
            float b0 = bias[c], b1 = bias[c + 1];
            *reinterpret_cast<float2*>(&g_qkv[(size_t)r0       * FQKV + c]) =
                make_float2(acc[mi][ni][0] + b0, acc[mi][ni][1] + b1);
            *reinterpret_cast<float2*>(&g_qkv[(size_t)(r0 + 8) * FQKV + c]) =
                make_float2(acc[mi][ni][2] + b0, acc[mi][ni][3] + b1);
        }
    }
}

// ===========================================================================
// Output projection: plain tf32, ldmatrix fragment loads (R5 version, ~85us)
// ===========================================================================
__global__ void __launch_bounds__(256) k_out(const float* __restrict__ w,
                                             const float* __restrict__ bias,
                                             float* __restrict__ out)
{
    extern __shared__ uint32_t smo[];
    uint32_t* Ah = smo;            // 128*36
    uint32_t* Bh = Ah + 128 * 36;  // 64*36

    const int row0 = blockIdx.y * 128, col0 = blockIdx.x * 64;
    const int t = threadIdx.x, warp = t >> 5, lane = t & 31;
    const int wm = warp >> 2, wn = warp & 3;
    const int g = lane >> 2, tg = lane & 3;
    const int lr = lane & 15, lc = (lane >> 4) << 2;

    const uint32_t aA = smaddr(Ah) + (uint32_t)((wm * 64 + lr) * 36 + lc) * 4;
    const uint32_t aB = smaddr(Bh) + (uint32_t)((wn * 16 + lr) * 36 + lc) * 4;

    float acc[4][2][4] = {};
    float4 pa[4], pb[2];

    #pragma unroll
    for (int i = 0; i < 4; i++) {
        int idx = t + i * 256;
        int r = idx >> 3, c4 = (idx & 7) * 4;
        pa[i] = *reinterpret_cast<const float4*>(&g_oh[(size_t)(row0 + r) * EMB + c4]);
    }
    #pragma unroll
    for (int i = 0; i < 2; i++) {
        int idx = t + i * 256;
        int r = idx >> 3, c4 = (idx & 7) * 4;
        pb[i] = *reinterpret_cast<const float4*>(&w[(size_t)(col0 + r) * EMB + c4]);
    }

    for (int k0 = 0; k0 < EMB; k0 += 32) {
        __syncthreads();
        #pragma unroll
        for (int i = 0; i < 4; i++) {
            int idx = t + i * 256;
            int r = idx >> 3, c4 = (idx & 7) * 4;
            Ah[r * 36 + c4 + 0] = f2tf(pa[i].x); Ah[r * 36 + c4 + 1] = f2tf(pa[i].y);
            Ah[r * 36 + c4 + 2] = f2tf(pa[i].z); Ah[r * 36 + c4 + 3] = f2tf(pa[i].w);
        }
        #pragma unroll
        for (int i = 0; i < 2; i++) {
            int idx = t + i * 256;
            int r = idx >> 3, c4 = (idx & 7) * 4;
            Bh[r * 36 + c4 + 0] = f2tf(pb[i].x); Bh[r * 36 + c4 + 1] = f2tf(pb[i].y);
            Bh[r * 36 + c4 + 2] = f2tf(pb[i].z); Bh[r * 36 + c4 + 3] = f2tf(pb[i].w);
        }
        __syncthreads();

        int kn = k0 + 32;
        if (kn < EMB) {
            #pragma unroll
            for (int i = 0; i < 4; i++) {
                int idx = t + i * 256;
                int r = idx >> 3, c4 = (idx & 7) * 4;
                pa[i] = *reinterpret_cast<const float4*>(&g_oh[(size_t)(row0 + r) * EMB + kn + c4]);
            }
            #pragma unroll
            for (int i = 0; i < 2; i++) {
                int idx = t + i * 256;
                int r = idx >> 3, c4 = (idx & 7) * 4;
                pb[i] = *reinterpret_cast<const float4*>(&w[(size_t)(col0 + r) * EMB + kn + c4]);
            }
        }

        #pragma unroll
        for (int ks = 0; ks < 4; ks++) {
            const uint32_t ko = (uint32_t)(ks * 8) * 4;
            uint32_t a[4][4], b[4];
            #pragma unroll
            for (int mi = 0; mi < 4; mi++)
                ldsm4(a[mi], aA + (uint32_t)(mi * 16 * 36) * 4 + ko);
            ldsm4(b, aB + ko);
            #pragma unroll
            for (int mi = 0; mi < 4; mi++)
                #pragma unroll
                for (int ni = 0; ni < 2; ni++)
                    mma8(acc[mi][ni], a[mi][0], a[mi][1], a[mi][2], a[mi][3],
                         b[ni], b[2 + ni]);
        }
    }

    #pragma unroll
    for (int mi = 0; mi < 4; mi++) {
        int r0 = row0 + wm * 64 + mi * 16 + g;
        #pragma unroll
        for (int ni = 0; ni < 2; ni++) {
            int c = col0 + wn * 16 + ni * 8 + 2 * tg;
            float b0 = bias[c], b1 = bias[c + 1];
            *reinterpret_cast<float2*>(&out[(size_t)r0       * EMB + c]) =
                make_float2(acc[mi][ni][0] + b0, acc[mi][ni][1] + b1);
            *reinterpret_cast<float2*>(&out[(size_t)(r0 + 8) * EMB + c]) =
                make_float2(acc[mi][ni][2] + b0, acc[mi][ni][3] + b1);
        }
    }
}

// ===========================================================================
// Fused attention (unchanged from R5): CTA = 32 query rows of one (b,h).
// ===========================================================================
#define SSTR 1036
#define KST  68
#define VST  72

__device__ __forceinline__ void issue_strip(const float* __restrict__ gp,
                                            float* buf, int s, int t, int stride)
{
    #pragma unroll
    for (int i = 0; i < 8; i++) {
        int idx = t + i * 256;
        int r = idx >> 4, c4 = (idx & 15) * 4;
        uint32_t dst = smaddr(buf + r * stride + c4);
        const float* src = gp + (size_t)(s * 128 + r) * FQKV + c4;
        cp16(dst, src);
    }
    asm volatile("cp.async.commit_group;" ::: "memory");
}

__global__ void __launch_bounds__(256) k_attn(float* __restrict__ attn)
{
    extern __shared__ float sm[];
    float* S  = sm;
    float* T0 = sm + 32 * SSTR;
    float* T1 = T0 + 128 * VST;

    const int bh = blockIdx.y;
    const int bb = bh / NHEAD, h = bh % NHEAD;
    const int row0 = blockIdx.x * 32;
    const int t = threadIdx.x, warp = t >> 5, lane = t & 31;
    const int g = lane >> 2, tg = lane & 3;
    const int wm = warp >> 2, wn = warp & 3;
    const int lr = lane & 15, lc = (lane >> 4) << 2;

    const float* Qg = g_qkv + ((size_t)bb * SEQ + row0) * FQKV + h * HDIM;
    const float* Kg = g_qkv + (size_t)bb * SEQ * FQKV + EMB     + h * HDIM;
    const float* Vg = g_qkv + (size_t)bb * SEQ * FQKV + 2 * EMB + h * HDIM;
    float* Sg = attn + ((size_t)bh * SEQ + row0) * SEQ;

    #pragma unroll
    for (int i = 0; i < 2; i++) {
        int idx = t + i * 256;
        int r = idx >> 4, c4 = (idx & 15) * 4;
        float4 v = *reinterpret_cast<const float4*>(&Qg[(size_t)r * FQKV + c4]);
        S[r * KST + c4 + 0] = v.x; S[r * KST + c4 + 1] = v.y;
        S[r * KST + c4 + 2] = v.z; S[r * KST + c4 + 3] = v.w;
    }
    __syncthreads();
    uint32_t qf[8][4];
    {
        const int rb = wm * 16;
        #pragma unroll
        for (int ks = 0; ks < 8; ks++) {
            int kb = ks * 8;
            qf[ks][0] = f2tf(S[(rb + g    ) * KST + kb + tg]);
            qf[ks][1] = f2tf(S[(rb + g + 8) * KST + kb + tg]);
            qf[ks][2] = f2tf(S[(rb + g    ) * KST + kb + tg + 4]);
            qf[ks][3] = f2tf(S[(rb + g + 8) * KST + kb + tg + 4]);
        }
    }

    issue_strip(Kg, T0, 0, t, KST);
    const uint32_t kfragoff = (uint32_t)((wn * 32 + lr) * KST + lc) * 4;

    for (int s = 0; s < 8; s++) {
        if (s < 7) {
            issue_strip(Kg, (s & 1) ? T0 : T1, s + 1, t, KST);
            asm volatile("cp.async.wait_group 1;" ::: "memory");
        } else {
            asm volatile("cp.async.wait_group 0;" ::: "memory");
        }
        __syncthreads();
        const float* Kb = (s & 1) ? T1 : T0;
        const uint32_t kbase = smaddr(Kb) + kfragoff;

        float acc[4][4] = {};
        #pragma unroll
        for (int ks = 0; ks < 8; ks++) {
            uint32_t b0[4], b1[4];
            ldsm4(b0, kbase + (uint32_t)(ks * 8) * 4);
            ldsm4(b1, kbase + (uint32_t)(16 * KST + ks * 8) * 4);
            mma8(acc[0], qf[ks][0], qf[ks][1], qf[ks][2], qf[ks][3], b0[0], b0[2]);
            mma8(acc[1], qf[ks][0], qf[ks][1], qf[ks][2], qf[ks][3], b0[1], b0[3]);
            mma8(acc[2], qf[ks][0], qf[ks][1], qf[ks][2], qf[ks][3], b1[0], b1[2]);
            mma8(acc[3], qf[ks][0], qf[ks][1], qf[ks][2], qf[ks][3], b1[1], b1[3]);
        }
        {
            int r = wm * 16 + g;
            #pragma unroll
            for (int ni = 0; ni < 4; ni++) {
                int c = s * 128 + wn * 32 + ni * 8 + 2 * tg;
                S[(size_t)r       * SSTR + c]     = acc[ni][0] * 0.125f;
                S[(size_t)r       * SSTR + c + 1] = acc[ni][1] * 0.125f;
                S[(size_t)(r + 8) * SSTR + c]     = acc[ni][2] * 0.125f;
                S[(size_t)(r + 8) * SSTR + c + 1] = acc[ni][3] * 0.125f;
            }
        }
        __syncthreads();
    }

    issue_strip(Vg, T0, 0, t, VST);

    #pragma unroll
    for (int j = 0; j < 4; j++) {
        int r = warp + j * 8;
        float* Sr = S + (size_t)r * SSTR;

        float m = -1e30f;
        #pragma unroll
        for (int it = 0; it < 8; it++) {
            float4 v = *reinterpret_cast<float4*>(&Sr[(it * 32 + lane) * 4]);
            m = fmaxf(m, fmaxf(fmaxf(v.x, v.y), fmaxf(v.z, v.w)));
        }
        #pragma unroll
        for (int o = 16; o > 0; o >>= 1) m = fmaxf(m, __shfl_xor_sync(0xffffffffu, m, o));

        float sum = 0.0f;
        #pragma unroll
        for (int it = 0; it < 8; it++) {
            float4 v = *reinterpret_cast<float4*>(&Sr[(it * 32 + lane) * 4]);
            v.x = __expf(v.x - m); v.y = __expf(v.y - m);
            v.z = __expf(v.z - m); v.w = __expf(v.w - m);
            sum += v.x + v.y + v.z + v.w;
            *reinterpret_cast<float4*>(&Sr[(it * 32 + lane) * 4]) = v;
        }
        #pragma unroll
        for (int o = 16; o > 0; o >>= 1) sum += __shfl_xor_sync(0xffffffffu, sum, o);
        float inv = 1.0f / sum;

        float* arow = Sg + (size_t)r * SEQ;
        #pragma unroll
        for (int it = 0; it < 8; it++) {
            float4 v = *reinterpret_cast<float4*>(&Sr[(it * 32 + lane) * 4]);
            v.x *= inv; v.y *= inv; v.z *= inv; v.w *= inv;
            *reinterpret_cast<float4*>(&arow[(it * 32 + lane) * 4]) = v;
            uint4 u = make_uint4(f2tf(v.x), f2tf(v.y), f2tf(v.z), f2tf(v.w));
            *reinterpret_cast<uint4*>(&Sr[(it * 32 + lane) * 4]) = u;
        }
    }

    const uint32_t pbase0 = smaddr(S) + (uint32_t)(lr * SSTR + lc) * 4;
    float acc2[2][4] = {};

    for (int s = 0; s < 8; s++) {
        if (s < 7) {
            issue_strip(Vg, (s & 1) ? T0 : T1, s + 1, t, VST);
            asm volatile("cp.async.wait_group 1;" ::: "memory");
        } else {
            asm volatile("cp.async.wait_group 0;" ::: "memory");
        }
        __syncthreads();
        const float* Vb = (s & 1) ? T1 : T0;
        const uint32_t* Vu = (const uint32_t*)Vb;
        const int vc = warp * 8 + g;

        #pragma unroll
        for (int ks = 0; ks < 16; ks++) {
            const int kb = ks * 8;
            uint32_t a0[4], a1[4];
            ldsm4(a0, pbase0 + (uint32_t)(s * 128 + kb) * 4);
            ldsm4(a1, pbase0 + (uint32_t)(16 * SSTR + s * 128 + kb) * 4);
            uint32_t b0 = Vu[(kb + tg    ) * VST + vc];
            uint32_t b1 = Vu[(kb + tg + 4) * VST + vc];
            mma8(acc2[0], a0[0], a0[1], a0[2], a0[3], b0, b1);
            mma8(acc2[1], a1[0], a1[1], a1[2], a1[3], b0, b1);
        }
        __syncthreads();
    }

    #pragma unroll
    for (int mi = 0; mi < 2; mi++) {
        int r = row0 + mi * 16 + g;
        int c = h * HDIM + warp * 8 + 2 * tg;
        *reinterpret_cast<float2*>(&g_oh[((size_t)bb * SEQ + r    ) * EMB + c]) =
            make_float2(acc2[mi][0], acc2[mi][1]);
        *reinterpret_cast<float2*>(&g_oh[((size_t)bb * SEQ + r + 8) * EMB + c]) =
            make_float2(acc2[mi][2], acc2[mi][3]);
    }
}

// ---------------------------------------------------------------------------
extern "C" void kernel_launch(void* const* d_in, const int* in_sizes, int n_in,
                              void* d_out, int out_size)
{
    const float* x     = (const float*)d_in[0];
    const float* w_qkv = (const float*)d_in[1];
    const float* b_qkv = (const float*)d_in[2];
    const float* w_out = (const float*)d_in[3];
    const float* b_out = (const float*)d_in[4];

    float* out  = (float*)d_out;
    float* attn = out + (size_t)MTOT * EMB;

    const int smem_qkv  = 2 * QKV_STAGE * 4;               // 61440
    const int smem_out  = (128 * 36 + 64 * 36) * 4;        // 27648
    const int smem_attn = (32 * SSTR + 2 * 128 * VST) * 4; // 206336

    static bool attr_done = false;
    if (!attr_done) {
        cudaFuncSetAttribute(k_qkv,  cudaFuncAttributeMaxDynamicSharedMemorySize, smem_qkv);
        cudaFuncSetAttribute(k_out,  cudaFuncAttributeMaxDynamicSharedMemorySize, smem_out);
        cudaFuncSetAttribute(k_attn, cudaFuncAttributeMaxDynamicSharedMemorySize, smem_attn);
        attr_done = true;
    }

    __nv_bfloat16 *xh, *xl, *wh, *wl;
    cudaGetSymbolAddress((void**)&xh, g_xh);
    cudaGetSymbolAddress((void**)&xl, g_xl);
    cudaGetSymbolAddress((void**)&wh, g_wh);
    cudaGetSymbolAddress((void**)&wl, g_wl);

    const int nx4 = MTOT * EMB / 4;    // 1572864
    const int nw4 = FQKV * EMB / 4;    // 442368

    k_split<<<(nx4 + 255) / 256, 256>>>(x,     xh, xl, nx4);
    k_split<<<(nw4 + 255) / 256, 256>>>(w_qkv, wh, wl, nw4);

    k_qkv <<<dim3(FQKV / 64, MTOT / 128), 256, smem_qkv >>>(b_qkv);
    k_attn<<<dim3(SEQ / 32, BHTOT),       256, smem_attn>>>(attn);
    k_out <<<dim3(EMB / 64, MTOT / 128),  256, smem_out >>>(w_out, b_out, out);
}

// round 8
// speedup vs baseline: 1.0336x; 1.0336x over previous
#include <cuda_runtime.h>
#include <cuda_bf16.h>
#include <math.h>
#include <stdint.h>

#define EMB   768
#define NHEAD 12
#define HDIM  64
#define SEQ   1024
#define BATCH 8
#define MTOT  (BATCH * SEQ)
#define FQKV  (3 * EMB)
#define BHTOT (BATCH * NHEAD)

__device__ float g_qkv[(size_t)MTOT * FQKV];   // 75.5 MB
__device__ float g_oh [(size_t)MTOT * EMB];    // 25.2 MB
__device__ __nv_bfloat16 g_xh[(size_t)MTOT * EMB];
__device__ __nv_bfloat16 g_xl[(size_t)MTOT * EMB];
__device__ __nv_bfloat16 g_wh[(size_t)FQKV * EMB];
__device__ __nv_bfloat16 g_wl[(size_t)FQKV * EMB];

__device__ __forceinline__ uint32_t f2tf(float x) {
    uint32_t r;
    asm("cvt.rna.tf32.f32 %0, %1;" : "=r"(r) : "f"(x));
    return r;
}

__device__ __forceinline__ uint32_t smaddr(const void* p) {
    return (uint32_t)__cvta_generic_to_shared(p);
}

__device__ __forceinline__ void ldsm4(uint32_t* r, uint32_t a) {
    asm volatile("ldmatrix.sync.aligned.m8n8.x4.shared.b16 {%0,%1,%2,%3}, [%4];"
                 : "=r"(r[0]), "=r"(r[1]), "=r"(r[2]), "=r"(r[3]) : "r"(a));
}

__device__ __forceinline__ void cp16(uint32_t dst, const void* src) {
    asm volatile("cp.async.cg.shared.global [%0], [%1], 16;" :: "r"(dst), "l"(src));
}

__device__ __forceinline__ void mma8(float* c,
                                     uint32_t a0, uint32_t a1, uint32_t a2, uint32_t a3,
                                     uint32_t b0, uint32_t b1)
{
    asm volatile(
        "mma.sync.aligned.m16n8k8.row.col.f32.tf32.tf32.f32 "
        "{%0,%1,%2,%3}, {%4,%5,%6,%7}, {%8,%9}, {%0,%1,%2,%3};\n"
        : "+f"(c[0]), "+f"(c[1]), "+f"(c[2]), "+f"(c[3])
        : "r"(a0), "r"(a1), "r"(a2), "r"(a3), "r"(b0), "r"(b1));
}

__device__ __forceinline__ void mma16(float* c, const uint32_t* a,
                                      uint32_t b0, uint32_t b1)
{
    asm volatile(
        "mma.sync.aligned.m16n8k16.row.col.f32.bf16.bf16.f32 "
        "{%0,%1,%2,%3}, {%4,%5,%6,%7}, {%8,%9}, {%0,%1,%2,%3};\n"
        : "+f"(c[0]), "+f"(c[1]), "+f"(c[2]), "+f"(c[3])
        : "r"(a[0]), "r"(a[1]), "r"(a[2]), "r"(a[3]), "r"(b0), "r"(b1));
}

// ===========================================================================
// Pre-split: fp32 -> bf16 hi + bf16 lo (residual).
// ===========================================================================
__global__ void __launch_bounds__(256) k_split(const float* __restrict__ src,
                                               __nv_bfloat16* __restrict__ hi,
                                               __nv_bfloat16* __restrict__ lo,
                                               int n4)
{
    int i = blockIdx.x * blockDim.x + threadIdx.x;
    if (i >= n4) return;
    float4 v = reinterpret_cast<const float4*>(src)[i];
    __nv_bfloat162 h0 = __floats2bfloat162_rn(v.x, v.y);
    __nv_bfloat162 h1 = __floats2bfloat162_rn(v.z, v.w);
    __nv_bfloat162 l0 = __floats2bfloat162_rn(v.x - __bfloat162float(h0.x),
                                              v.y - __bfloat162float(h0.y));
    __nv_bfloat162 l1 = __floats2bfloat162_rn(v.z - __bfloat162float(h1.x),
                                              v.w - __bfloat162float(h1.y));
    reinterpret_cast<__nv_bfloat162*>(hi)[i * 2]     = h0;
    reinterpret_cast<__nv_bfloat162*>(hi)[i * 2 + 1] = h1;
    reinterpret_cast<__nv_bfloat162*>(lo)[i * 2]     = l0;
    reinterpret_cast<__nv_bfloat162*>(lo)[i * 2 + 1] = l1;
}

// ===========================================================================
// QKV projection: 128x128 block, warp tile 64x32, pre-split bf16,
// cp.async double-buffered. 8 warps (2m x 4n).
// ===========================================================================
#define PSTR 20
#define QKV_STAGE (4 * 128 * PSTR)   // Ah,Al,Bh,Bl each 128*PSTR words

__device__ __forceinline__ void qkv_issue(uint32_t base, int row0, int col0,
                                          int k0, int t)
{
    #pragma unroll
    for (int i = 0; i < 2; i++) {
        int idx = t + i * 256;
        int r = idx >> 2, seg = idx & 3;
        uint32_t dst = base + (uint32_t)(r * PSTR + seg * 4) * 4;
        size_t so = (size_t)(row0 + r) * EMB + k0 + seg * 8;
        cp16(dst,                  g_xh + so);
        cp16(dst + 128 * PSTR * 4, g_xl + so);
    }
    #pragma unroll
    for (int i = 0; i < 2; i++) {
        int idx = t + i * 256;
        int r = idx >> 2, seg = idx & 3;
        uint32_t dst = base + (uint32_t)(2 * 128 * PSTR + r * PSTR + seg * 4) * 4;
        size_t so = (size_t)(col0 + r) * EMB + k0 + seg * 8;
        cp16(dst,                  g_wh + so);
        cp16(dst + 128 * PSTR * 4, g_wl + so);
    }
    asm volatile("cp.async.commit_group;" ::: "memory");
}

__global__ void __launch_bounds__(256, 2) k_qkv(const float* __restrict__ bias)
{
    extern __shared__ uint32_t smu[];

    const int row0 = blockIdx.y * 128, col0 = blockIdx.x * 128;
    const int t = threadIdx.x, warp = t >> 5, lane = t & 31;
    const int wm = warp >> 2, wn = warp & 3;
    const int g = lane >> 2, tg = lane & 3;
    const int lr = lane & 15, lc = (lane >> 4) << 2;

    const uint32_t sbase = smaddr(smu);
    float acc[4][4][4] = {};

    qkv_issue(sbase, row0, col0, 0, t);

    for (int s = 0; s < 24; s++) {
        if (s < 23) {
            qkv_issue(sbase + ((s + 1) & 1) * (QKV_STAGE * 4), row0, col0,
                      (s + 1) * 32, t);
            asm volatile("cp.async.wait_group 1;" ::: "memory");
        } else {
            asm volatile("cp.async.wait_group 0;" ::: "memory");
        }
        __syncthreads();

        const uint32_t sb  = sbase + (s & 1) * (QKV_STAGE * 4);
        const uint32_t aAh = sb + (uint32_t)((wm * 64 + lr) * PSTR + lc) * 4;
        const uint32_t aAl = aAh + 128 * PSTR * 4;
        const uint32_t aBh = sb + (uint32_t)(2 * 128 * PSTR + (wn * 32 + lr) * PSTR + lc) * 4;
        const uint32_t aBl = aBh + 128 * PSTR * 4;

        #pragma unroll
        for (int ks = 0; ks < 2; ks++) {
            const uint32_t po = (uint32_t)(ks * 8) * 4;
            uint32_t bh[2][4], bl[2][4];
            #pragma unroll
            for (int j = 0; j < 2; j++) {
                ldsm4(bh[j], aBh + (uint32_t)(j * 16 * PSTR) * 4 + po);
                ldsm4(bl[j], aBl + (uint32_t)(j * 16 * PSTR) * 4 + po);
            }
            #pragma unroll
            for (int mi = 0; mi < 4; mi++) {
                uint32_t ah[4], al[4];
                ldsm4(ah, aAh + (uint32_t)(mi * 16 * PSTR) * 4 + po);
                ldsm4(al, aAl + (uint32_t)(mi * 16 * PSTR) * 4 + po);
                #pragma unroll
                for (int j = 0; j < 2; j++)
                    #pragma unroll
                    for (int ni = 0; ni < 2; ni++) {
                        float* c = acc[mi][j * 2 + ni];
                        mma16(c, ah, bh[j][ni], bh[j][2 + ni]);
                        mma16(c, ah, bl[j][ni], bl[j][2 + ni]);
                        mma16(c, al, bh[j][ni], bh[j][2 + ni]);
                    }
            }
        }
        __syncthreads();
    }

    #pragma unroll
    for (int mi = 0; mi < 4; mi++) {
        int r0 = row0 + wm * 64 + mi * 16 + g;
        #pragma unroll
        for (int q = 0; q < 4; q++) {
            int c = col0 + wn * 32 + q * 8 + 2 * tg;
            float b0 = bias[c], b1 = bias[c + 1];
            *reinterpret_cast<float2*>(&g_qkv[(size_t)r0       * FQKV + c]) =
                make_float2(acc[mi][q][0] + b0, acc[mi][q][1] + b1);
            *reinterpret_cast<float2*>(&g_qkv[(size_t)(r0 + 8) * FQKV + c]) =
                make_float2(acc[mi][q][2] + b0, acc[mi][q][3] + b1);
        }
    }
}

// ===========================================================================
// Output projection: plain tf32, ldmatrix (unchanged, ~85us)
// ===========================================================================
__global__ void __launch_bounds__(256) k_out(const float* __restrict__ w,
                                             const float* __restrict__ bias,
                                             float* __restrict__ out)
{
    extern __shared__ uint32_t smo[];
    uint32_t* Ah = smo;            // 128*36
    uint32_t* Bh = Ah + 128 * 36;  // 64*36

    const int row0 = blockIdx.y * 128, col0 = blockIdx.x * 64;
    const int t = threadIdx.x, warp = t >> 5, lane = t & 31;
    const int wm = warp >> 2, wn = warp & 3;
    const int g = lane >> 2, tg = lane & 3;
    const int lr = lane & 15, lc = (lane >> 4) << 2;

    const uint32_t aA = smaddr(Ah) + (uint32_t)((wm * 64 + lr) * 36 + lc) * 4;
    const uint32_t aB = smaddr(Bh) + (uint32_t)((wn * 16 + lr) * 36 + lc) * 4;

    float acc[4][2][4] = {};
    float4 pa[4], pb[2];

    #pragma unroll
    for (int i = 0; i < 4; i++) {
        int idx = t + i * 256;
        int r = idx >> 3, c4 = (idx & 7) * 4;
        pa[i] = *reinterpret_cast<const float4*>(&g_oh[(size_t)(row0 + r) * EMB + c4]);
    }
    #pragma unroll
    for (int i = 0; i < 2; i++) {
        int idx = t + i * 256;
        int r = idx >> 3, c4 = (idx & 7) * 4;
        pb[i] = *reinterpret_cast<const float4*>(&w[(size_t)(col0 + r) * EMB + c4]);
    }

    for (int k0 = 0; k0 < EMB; k0 += 32) {
        __syncthreads();
        #pragma unroll
        for (int i = 0; i < 4; i++) {
            int idx = t + i * 256;
            int r = idx >> 3, c4 = (idx & 7) * 4;
            Ah[r * 36 + c4 + 0] = f2tf(pa[i].x); Ah[r * 36 + c4 + 1] = f2tf(pa[i].y);
            Ah[r * 36 + c4 + 2] = f2tf(pa[i].z); Ah[r * 36 + c4 + 3] = f2tf(pa[i].w);
        }
        #pragma unroll
        for (int i = 0; i < 2; i++) {
            int idx = t + i * 256;
            int r = idx >> 3, c4 = (idx & 7) * 4;
            Bh[r * 36 + c4 + 0] = f2tf(pb[i].x); Bh[r * 36 + c4 + 1] = f2tf(pb[i].y);
            Bh[r * 36 + c4 + 2] = f2tf(pb[i].z); Bh[r * 36 + c4 + 3] = f2tf(pb[i].w);
        }
        __syncthreads();

        int kn = k0 + 32;
        if (kn < EMB) {
            #pragma unroll
            for (int i = 0; i < 4; i++) {
                int idx = t + i * 256;
                int r = idx >> 3, c4 = (idx & 7) * 4;
                pa[i] = *reinterpret_cast<const float4*>(&g_oh[(size_t)(row0 + r) * EMB + kn + c4]);
            }
            #pragma unroll
            for (int i = 0; i < 2; i++) {
                int idx = t + i * 256;
                int r = idx >> 3, c4 = (idx & 7) * 4;
                pb[i] = *reinterpret_cast<const float4*>(&w[(size_t)(col0 + r) * EMB + kn + c4]);
            }
        }

        #pragma unroll
        for (int ks = 0; ks < 4; ks++) {
            const uint32_t ko = (uint32_t)(ks * 8) * 4;
            uint32_t a[4][4], b[4];
            #pragma unroll
            for (int mi = 0; mi < 4; mi++)
                ldsm4(a[mi], aA + (uint32_t)(mi * 16 * 36) * 4 + ko);
            ldsm4(b, aB + ko);
            #pragma unroll
            for (int mi = 0; mi < 4; mi++)
                #pragma unroll
                for (int ni = 0; ni < 2; ni++)
                    mma8(acc[mi][ni], a[mi][0], a[mi][1], a[mi][2], a[mi][3],
                         b[ni], b[2 + ni]);
        }
    }

    #pragma unroll
    for (int mi = 0; mi < 4; mi++) {
        int r0 = row0 + wm * 64 + mi * 16 + g;
        #pragma unroll
        for (int ni = 0; ni < 2; ni++) {
            int c = col0 + wn * 16 + ni * 8 + 2 * tg;
            float b0 = bias[c], b1 = bias[c + 1];
            *reinterpret_cast<float2*>(&out[(size_t)r0       * EMB + c]) =
                make_float2(acc[mi][ni][0] + b0, acc[mi][ni][1] + b1);
            *reinterpret_cast<float2*>(&out[(size_t)(r0 + 8) * EMB + c]) =
                make_float2(acc[mi][ni][2] + b0, acc[mi][ni][3] + b1);
        }
    }
}

// ===========================================================================
// Fused attention, 512 threads (16 warps): CTA = 32 query rows of one (b,h).
// ===========================================================================
#define SSTR 1036
#define KST  68
#define VST  72

__device__ __forceinline__ void issue_strip(const float* __restrict__ gp,
                                            float* buf, int s, int t, int stride)
{
    #pragma unroll
    for (int i = 0; i < 4; i++) {
        int idx = t + i * 512;
        int r = idx >> 4, c4 = (idx & 15) * 4;
        uint32_t dst = smaddr(buf + r * stride + c4);
        const float* src = gp + (size_t)(s * 128 + r) * FQKV + c4;
        cp16(dst, src);
    }
    asm volatile("cp.async.commit_group;" ::: "memory");
}

__global__ void __launch_bounds__(512) k_attn(float* __restrict__ attn)
{
    extern __shared__ float sm[];
    float* S  = sm;
    float* T0 = sm + 32 * SSTR;
    float* T1 = T0 + 128 * VST;

    const int bh = blockIdx.y;
    const int bb = bh / NHEAD, h = bh % NHEAD;
    const int row0 = blockIdx.x * 32;
    const int t = threadIdx.x, warp = t >> 5, lane = t & 31;
    const int g = lane >> 2, tg = lane & 3;
    const int wm = warp >> 3;          // 0..1  (16-row block)
    const int wn = warp & 7;           // 0..7
    const int lr = lane & 15, lc = (lane >> 4) << 2;

    const float* Qg = g_qkv + ((size_t)bb * SEQ + row0) * FQKV + h * HDIM;
    const float* Kg = g_qkv + (size_t)bb * SEQ * FQKV + EMB     + h * HDIM;
    const float* Vg = g_qkv + (size_t)bb * SEQ * FQKV + 2 * EMB + h * HDIM;
    float* Sg = attn + ((size_t)bh * SEQ + row0) * SEQ;

    // ---- stage Q (32x64) into S region, pin tf32 fragments ----
    {
        int r = t >> 4, c4 = (t & 15) * 4;
        float4 v = *reinterpret_cast<const float4*>(&Qg[(size_t)r * FQKV + c4]);
        S[r * KST + c4 + 0] = v.x; S[r * KST + c4 + 1] = v.y;
        S[r * KST + c4 + 2] = v.z; S[r * KST + c4 + 3] = v.w;
    }
    __syncthreads();
    uint32_t qf[8][4];
    {
        const int rb = wm * 16;
        #pragma unroll
        for (int ks = 0; ks < 8; ks++) {
            int kb = ks * 8;
            qf[ks][0] = f2tf(S[(rb + g    ) * KST + kb + tg]);
            qf[ks][1] = f2tf(S[(rb + g + 8) * KST + kb + tg]);
            qf[ks][2] = f2tf(S[(rb + g    ) * KST + kb + tg + 4]);
            qf[ks][3] = f2tf(S[(rb + g + 8) * KST + kb + tg + 4]);
        }
    }

    // ---- QK^T: 8 strips of 128 keys, warp covers 16 cols ----
    issue_strip(Kg, T0, 0, t, KST);
    const uint32_t kfragoff = (uint32_t)((wn * 16 + lr) * KST + lc) * 4;

    for (int s = 0; s < 8; s++) {
        if (s < 7) {
            issue_strip(Kg, (s & 1) ? T0 : T1, s + 1, t, KST);
            asm volatile("cp.async.wait_group 1;" ::: "memory");
        } else {
            asm volatile("cp.async.wait_group 0;" ::: "memory");
        }
        __syncthreads();
        const float* Kb = (s & 1) ? T1 : T0;
        const uint32_t kbase = smaddr(Kb) + kfragoff;

        float acc[2][4] = {};
        #pragma unroll
        for (int ks = 0; ks < 8; ks++) {
            uint32_t b[4];
            ldsm4(b, kbase + (uint32_t)(ks * 8) * 4);
            mma8(acc[0], qf[ks][0], qf[ks][1], qf[ks][2], qf[ks][3], b[0], b[2]);
            mma8(acc[1], qf[ks][0], qf[ks][1], qf[ks][2], qf[ks][3], b[1], b[3]);
        }
        {
            int r = wm * 16 + g;
            #pragma unroll
            for (int ni = 0; ni < 2; ni++) {
                int c = s * 128 + wn * 16 + ni * 8 + 2 * tg;
                S[(size_t)r       * SSTR + c]     = acc[ni][0] * 0.125f;
                S[(size_t)r       * SSTR + c + 1] = acc[ni][1] * 0.125f;
                S[(size_t)(r + 8) * SSTR + c]     = acc[ni][2] * 0.125f;
                S[(size_t)(r + 8) * SSTR + c + 1] = acc[ni][3] * 0.125f;
            }
        }
        __syncthreads();
    }

    issue_strip(Vg, T0, 0, t, VST);   // prefetch V strip 0 under softmax

    // ---- softmax: 16 warps x 2 rows ----
    #pragma unroll
    for (int j = 0; j < 2; j++) {
        int r = warp * 2 + j;
        float* Sr = S + (size_t)r * SSTR;

        float m = -1e30f;
        #pragma unroll
        for (int it = 0; it < 8; it++) {
            float4 v = *reinterpret_cast<float4*>(&Sr[(it * 32 + lane) * 4]);
            m = fmaxf(m, fmaxf(fmaxf(v.x, v.y), fmaxf(v.z, v.w)));
        }
        #pragma unroll
        for (int o = 16; o > 0; o >>= 1) m = fmaxf(m, __shfl_xor_sync(0xffffffffu, m, o));

        float sum = 0.0f;
        #pragma unroll
        for (int it = 0; it < 8; it++) {
            float4 v = *reinterpret_cast<float4*>(&Sr[(it * 32 + lane) * 4]);
            v.x = __expf(v.x - m); v.y = __expf(v.y - m);
            v.z = __expf(v.z - m); v.w = __expf(v.w - m);
            sum += v.x + v.y + v.z + v.w;
            *reinterpret_cast<float4*>(&Sr[(it * 32 + lane) * 4]) = v;
        }
        #pragma unroll
        for (int o = 16; o > 0; o >>= 1) sum += __shfl_xor_sync(0xffffffffu, sum, o);
        float inv = 1.0f / sum;

        float* arow = Sg + (size_t)r * SEQ;
        #pragma unroll
        for (int it = 0; it < 8; it++) {
            float4 v = *reinterpret_cast<float4*>(&Sr[(it * 32 + lane) * 4]);
            v.x *= inv; v.y *= inv; v.z *= inv; v.w *= inv;
            *reinterpret_cast<float4*>(&arow[(it * 32 + lane) * 4]) = v;
            uint4 u = make_uint4(f2tf(v.x), f2tf(v.y), f2tf(v.z), f2tf(v.w));
            *reinterpret_cast<uint4*>(&Sr[(it * 32 + lane) * 4]) = u;
        }
    }

    // ---- PV: warp = m16 x n8 tile ----
    const uint32_t pbase = smaddr(S) + (uint32_t)((wm * 16 + lr) * SSTR + lc) * 4;
    const int vc = wn * 8 + g;
    float acc2[4] = {};

    for (int s = 0; s < 8; s++) {
        if (s < 7) {
            issue_strip(Vg, (s & 1) ? T0 : T1, s + 1, t, VST);
            asm volatile("cp.async.wait_group 1;" ::: "memory");
        } else {
            asm volatile("cp.async.wait_group 0;" ::: "memory");
        }
        __syncthreads();
        const uint32_t* Vu = (const uint32_t*)((s & 1) ? T1 : T0);

        #pragma unroll
        for (int ks = 0; ks < 16; ks++) {
            const int kb = ks * 8;
            uint32_t a[4];
            ldsm4(a, pbase + (uint32_t)(s * 128 + kb) * 4);
            uint32_t b0 = Vu[(kb + tg    ) * VST + vc];
            uint32_t b1 = Vu[(kb + tg + 4) * VST + vc];
            mma8(acc2, a[0], a[1], a[2], a[3], b0, b1);
        }
        __syncthreads();
    }

    {
        int r = row0 + wm * 16 + g;
        int c = h * HDIM + wn * 8 + 2 * tg;
        *reinterpret_cast<float2*>(&g_oh[((size_t)bb * SEQ + r    ) * EMB + c]) =
            make_float2(acc2[0], acc2[1]);
        *reinterpret_cast<float2*>(&g_oh[((size_t)bb * SEQ + r + 8) * EMB + c]) =
            make_float2(acc2[2], acc2[3]);
    }
}

// ---------------------------------------------------------------------------
extern "C" void kernel_launch(void* const* d_in, const int* in_sizes, int n_in,
                              void* d_out, int out_size)
{
    const float* x     = (const float*)d_in[0];
    const float* w_qkv = (const float*)d_in[1];
    const float* b_qkv = (const float*)d_in[2];
    const float* w_out = (const float*)d_in[3];
    const float* b_out = (const float*)d_in[4];

    float* out  = (float*)d_out;
    float* attn = out + (size_t)MTOT * EMB;

    const int smem_qkv  = 2 * QKV_STAGE * 4;               // 81920
    const int smem_out  = (128 * 36 + 64 * 36) * 4;        // 27648
    const int smem_attn = (32 * SSTR + 2 * 128 * VST) * 4; // 206336

    static bool attr_done = false;
    if (!attr_done) {
        cudaFuncSetAttribute(k_qkv,  cudaFuncAttributeMaxDynamicSharedMemorySize, smem_qkv);
        cudaFuncSetAttribute(k_out,  cudaFuncAttributeMaxDynamicSharedMemorySize, smem_out);
        cudaFuncSetAttribute(k_attn, cudaFuncAttributeMaxDynamicSharedMemorySize, smem_attn);
        attr_done = true;
    }

    __nv_bfloat16 *xh, *xl, *wh, *wl;
    cudaGetSymbolAddress((void**)&xh, g_xh);
    cudaGetSymbolAddress((void**)&xl, g_xl);
    cudaGetSymbolAddress((void**)&wh, g_wh);
    cudaGetSymbolAddress((void**)&wl, g_wl);

    const int nx4 = MTOT * EMB / 4;
    const int nw4 = FQKV * EMB / 4;

    k_split<<<(nx4 + 255) / 256, 256>>>(x,     xh, xl, nx4);
    k_split<<<(nw4 + 255) / 256, 256>>>(w_qkv, wh, wl, nw4);

    k_qkv <<<dim3(FQKV / 128, MTOT / 128), 256, smem_qkv >>>(b_qkv);
    k_attn<<<dim3(SEQ / 32, BHTOT),        512, smem_attn>>>(attn);
    k_out <<<dim3(EMB / 64, MTOT / 128),   256, smem_out >>>(w_out, b_out, out);
}

// round 9
// speedup vs baseline: 1.0537x; 1.0194x over previous
#include <cuda_runtime.h>
#include <cuda_bf16.h>
#include <math.h>
#include <stdint.h>

#define EMB   768
#define NHEAD 12
#define HDIM  64
#define SEQ   1024
#define BATCH 8
#define MTOT  (BATCH * SEQ)
#define FQKV  (3 * EMB)
#define BHTOT (BATCH * NHEAD)

__device__ float g_qkv[(size_t)MTOT * FQKV];   // 75.5 MB
__device__ float g_oh [(size_t)MTOT * EMB];    // 25.2 MB
__device__ __nv_bfloat16 g_vh[(size_t)MTOT * EMB];   // V in bf16 (head-sliced cols)
__device__ __nv_bfloat16 g_xh[(size_t)MTOT * EMB];
__device__ __nv_bfloat16 g_xl[(size_t)MTOT * EMB];
__device__ __nv_bfloat16 g_wh[(size_t)FQKV * EMB];
__device__ __nv_bfloat16 g_wl[(size_t)FQKV * EMB];

__device__ __forceinline__ uint32_t f2tf(float x) {
    uint32_t r;
    asm("cvt.rna.tf32.f32 %0, %1;" : "=r"(r) : "f"(x));
    return r;
}

__device__ __forceinline__ uint32_t smaddr(const void* p) {
    return (uint32_t)__cvta_generic_to_shared(p);
}

__device__ __forceinline__ void ldsm4(uint32_t* r, uint32_t a) {
    asm volatile("ldmatrix.sync.aligned.m8n8.x4.shared.b16 {%0,%1,%2,%3}, [%4];"
                 : "=r"(r[0]), "=r"(r[1]), "=r"(r[2]), "=r"(r[3]) : "r"(a));
}

__device__ __forceinline__ void ldsm2t(uint32_t& r0, uint32_t& r1, uint32_t a) {
    asm volatile("ldmatrix.sync.aligned.m8n8.x2.trans.shared.b16 {%0,%1}, [%2];"
                 : "=r"(r0), "=r"(r1) : "r"(a));
}

__device__ __forceinline__ void cp16(uint32_t dst, const void* src) {
    asm volatile("cp.async.cg.shared.global [%0], [%1], 16;" :: "r"(dst), "l"(src));
}

__device__ __forceinline__ void mma8(float* c,
                                     uint32_t a0, uint32_t a1, uint32_t a2, uint32_t a3,
                                     uint32_t b0, uint32_t b1)
{
    asm volatile(
        "mma.sync.aligned.m16n8k8.row.col.f32.tf32.tf32.f32 "
        "{%0,%1,%2,%3}, {%4,%5,%6,%7}, {%8,%9}, {%0,%1,%2,%3};\n"
        : "+f"(c[0]), "+f"(c[1]), "+f"(c[2]), "+f"(c[3])
        : "r"(a0), "r"(a1), "r"(a2), "r"(a3), "r"(b0), "r"(b1));
}

__device__ __forceinline__ void mma16(float* c, const uint32_t* a,
                                      uint32_t b0, uint32_t b1)
{
    asm volatile(
        "mma.sync.aligned.m16n8k16.row.col.f32.bf16.bf16.f32 "
        "{%0,%1,%2,%3}, {%4,%5,%6,%7}, {%8,%9}, {%0,%1,%2,%3};\n"
        : "+f"(c[0]), "+f"(c[1]), "+f"(c[2]), "+f"(c[3])
        : "r"(a[0]), "r"(a[1]), "r"(a[2]), "r"(a[3]), "r"(b0), "r"(b1));
}

// ===========================================================================
// Pre-split: fp32 -> bf16 hi + lo
// ===========================================================================
__global__ void __launch_bounds__(256) k_split(const float* __restrict__ src,
                                               __nv_bfloat16* __restrict__ hi,
                                               __nv_bfloat16* __restrict__ lo,
                                               int n4)
{
    int i = blockIdx.x * blockDim.x + threadIdx.x;
    if (i >= n4) return;
    float4 v = reinterpret_cast<const float4*>(src)[i];
    __nv_bfloat162 h0 = __floats2bfloat162_rn(v.x, v.y);
    __nv_bfloat162 h1 = __floats2bfloat162_rn(v.z, v.w);
    __nv_bfloat162 l0 = __floats2bfloat162_rn(v.x - __bfloat162float(h0.x),
                                              v.y - __bfloat162float(h0.y));
    __nv_bfloat162 l1 = __floats2bfloat162_rn(v.z - __bfloat162float(h1.x),
                                              v.w - __bfloat162float(h1.y));
    reinterpret_cast<__nv_bfloat162*>(hi)[i * 2]     = h0;
    reinterpret_cast<__nv_bfloat162*>(hi)[i * 2 + 1] = h1;
    reinterpret_cast<__nv_bfloat162*>(lo)[i * 2]     = l0;
    reinterpret_cast<__nv_bfloat162*>(lo)[i * 2 + 1] = l1;
}

// ===========================================================================
// QKV projection (R8 version) + bf16 V side-copy in epilogue
// ===========================================================================
#define PSTR 20
#define QKV_STAGE (4 * 128 * PSTR)

__device__ __forceinline__ void qkv_issue(uint32_t base, int row0, int col0,
                                          int k0, int t)
{
    #pragma unroll
    for (int i = 0; i < 2; i++) {
        int idx = t + i * 256;
        int r = idx >> 2, seg = idx & 3;
        uint32_t dst = base + (uint32_t)(r * PSTR + seg * 4) * 4;
        size_t so = (size_t)(row0 + r) * EMB + k0 + seg * 8;
        cp16(dst,                  g_xh + so);
        cp16(dst + 128 * PSTR * 4, g_xl + so);
    }
    #pragma unroll
    for (int i = 0; i < 2; i++) {
        int idx = t + i * 256;
        int r = idx >> 2, seg = idx & 3;
        uint32_t dst = base + (uint32_t)(2 * 128 * PSTR + r * PSTR + seg * 4) * 4;
        size_t so = (size_t)(col0 + r) * EMB + k0 + seg * 8;
        cp16(dst,                  g_wh + so);
        cp16(dst + 128 * PSTR * 4, g_wl + so);
    }
    asm volatile("cp.async.commit_group;" ::: "memory");
}

__global__ void __launch_bounds__(256, 2) k_qkv(const float* __restrict__ bias)
{
    extern __shared__ uint32_t smu[];

    const int row0 = blockIdx.y * 128, col0 = blockIdx.x * 128;
    const int t = threadIdx.x, warp = t >> 5, lane = t & 31;
    const int wm = warp >> 2, wn = warp & 3;
    const int g = lane >> 2, tg = lane & 3;
    const int lr = lane & 15, lc = (lane >> 4) << 2;

    const uint32_t sbase = smaddr(smu);
    float acc[4][4][4] = {};

    qkv_issue(sbase, row0, col0, 0, t);

    for (int s = 0; s < 24; s++) {
        if (s < 23) {
            qkv_issue(sbase + ((s + 1) & 1) * (QKV_STAGE * 4), row0, col0,
                      (s + 1) * 32, t);
            asm volatile("cp.async.wait_group 1;" ::: "memory");
        } else {
            asm volatile("cp.async.wait_group 0;" ::: "memory");
        }
        __syncthreads();

        const uint32_t sb  = sbase + (s & 1) * (QKV_STAGE * 4);
        const uint32_t aAh = sb + (uint32_t)((wm * 64 + lr) * PSTR + lc) * 4;
        const uint32_t aAl = aAh + 128 * PSTR * 4;
        const uint32_t aBh = sb + (uint32_t)(2 * 128 * PSTR + (wn * 32 + lr) * PSTR + lc) * 4;
        const uint32_t aBl = aBh + 128 * PSTR * 4;

        #pragma unroll
        for (int ks = 0; ks < 2; ks++) {
            const uint32_t po = (uint32_t)(ks * 8) * 4;
            uint32_t bh[2][4], bl[2][4];
            #pragma unroll
            for (int j = 0; j < 2; j++) {
                ldsm4(bh[j], aBh + (uint32_t)(j * 16 * PSTR) * 4 + po);
                ldsm4(bl[j], aBl + (uint32_t)(j * 16 * PSTR) * 4 + po);
            }
            #pragma unroll
            for (int mi = 0; mi < 4; mi++) {
                uint32_t ah[4], al[4];
                ldsm4(ah, aAh + (uint32_t)(mi * 16 * PSTR) * 4 + po);
                ldsm4(al, aAl + (uint32_t)(mi * 16 * PSTR) * 4 + po);
                #pragma unroll
                for (int j = 0; j < 2; j++)
                    #pragma unroll
                    for (int ni = 0; ni < 2; ni++) {
                        float* c = acc[mi][j * 2 + ni];
                        mma16(c, ah, bh[j][ni], bh[j][2 + ni]);
                        mma16(c, ah, bl[j][ni], bl[j][2 + ni]);
                        mma16(c, al, bh[j][ni], bh[j][2 + ni]);
                    }
            }
        }
        __syncthreads();
    }

    const bool isV = (col0 >= 2 * EMB);
    #pragma unroll
    for (int mi = 0; mi < 4; mi++) {
        int r0 = row0 + wm * 64 + mi * 16 + g;
        #pragma unroll
        for (int q = 0; q < 4; q++) {
            int c = col0 + wn * 32 + q * 8 + 2 * tg;
            float b0 = bias[c], b1 = bias[c + 1];
            float v00 = acc[mi][q][0] + b0, v01 = acc[mi][q][1] + b1;
            float v10 = acc[mi][q][2] + b0, v11 = acc[mi][q][3] + b1;
            *reinterpret_cast<float2*>(&g_qkv[(size_t)r0       * FQKV + c]) = make_float2(v00, v01);
            *reinterpret_cast<float2*>(&g_qkv[(size_t)(r0 + 8) * FQKV + c]) = make_float2(v10, v11);
            if (isV) {
                int cv = c - 2 * EMB;
                *reinterpret_cast<__nv_bfloat162*>(&g_vh[(size_t)r0       * EMB + cv]) =
                    __floats2bfloat162_rn(v00, v01);
                *reinterpret_cast<__nv_bfloat162*>(&g_vh[(size_t)(r0 + 8) * EMB + cv]) =
                    __floats2bfloat162_rn(v10, v11);
            }
        }
    }
}

// ===========================================================================
// Output projection (unchanged)
// ===========================================================================
__global__ void __launch_bounds__(256) k_out(const float* __restrict__ w,
                                             const float* __restrict__ bias,
                                             float* __restrict__ out)
{
    extern __shared__ uint32_t smo[];
    uint32_t* Ah = smo;
    uint32_t* Bh = Ah + 128 * 36;

    const int row0 = blockIdx.y * 128, col0 = blockIdx.x * 64;
    const int t = threadIdx.x, warp = t >> 5, lane = t & 31;
    const int wm = warp >> 2, wn = warp & 3;
    const int g = lane >> 2, tg = lane & 3;
    const int lr = lane & 15, lc = (lane >> 4) << 2;

    const uint32_t aA = smaddr(Ah) + (uint32_t)((wm * 64 + lr) * 36 + lc) * 4;
    const uint32_t aB = smaddr(Bh) + (uint32_t)((wn * 16 + lr) * 36 + lc) * 4;

    float acc[4][2][4] = {};
    float4 pa[4], pb[2];

    #pragma unroll
    for (int i = 0; i < 4; i++) {
        int idx = t + i * 256;
        int r = idx >> 3, c4 = (idx & 7) * 4;
        pa[i] = *reinterpret_cast<const float4*>(&g_oh[(size_t)(row0 + r) * EMB + c4]);
    }
    #pragma unroll
    for (int i = 0; i < 2; i++) {
        int idx = t + i * 256;
        int r = idx >> 3, c4 = (idx & 7) * 4;
        pb[i] = *reinterpret_cast<const float4*>(&w[(size_t)(col0 + r) * EMB + c4]);
    }

    for (int k0 = 0; k0 < EMB; k0 += 32) {
        __syncthreads();
        #pragma unroll
        for (int i = 0; i < 4; i++) {
            int idx = t + i * 256;
            int r = idx >> 3, c4 = (idx & 7) * 4;
            Ah[r * 36 + c4 + 0] = f2tf(pa[i].x); Ah[r * 36 + c4 + 1] = f2tf(pa[i].y);
            Ah[r * 36 + c4 + 2] = f2tf(pa[i].z); Ah[r * 36 + c4 + 3] = f2tf(pa[i].w);
        }
        #pragma unroll
        for (int i = 0; i < 2; i++) {
            int idx = t + i * 256;
            int r = idx >> 3, c4 = (idx & 7) * 4;
            Bh[r * 36 + c4 + 0] = f2tf(pb[i].x); Bh[r * 36 + c4 + 1] = f2tf(pb[i].y);
            Bh[r * 36 + c4 + 2] = f2tf(pb[i].z); Bh[r * 36 + c4 + 3] = f2tf(pb[i].w);
        }
        __syncthreads();

        int kn = k0 + 32;
        if (kn < EMB) {
            #pragma unroll
            for (int i = 0; i < 4; i++) {
                int idx = t + i * 256;
                int r = idx >> 3, c4 = (idx & 7) * 4;
                pa[i] = *reinterpret_cast<const float4*>(&g_oh[(size_t)(row0 + r) * EMB + kn + c4]);
            }
            #pragma unroll
            for (int i = 0; i < 2; i++) {
                int idx = t + i * 256;
                int r = idx >> 3, c4 = (idx & 7) * 4;
                pb[i] = *reinterpret_cast<const float4*>(&w[(size_t)(col0 + r) * EMB + kn + c4]);
            }
        }

        #pragma unroll
        for (int ks = 0; ks < 4; ks++) {
            const uint32_t ko = (uint32_t)(ks * 8) * 4;
            uint32_t a[4][4], b[4];
            #pragma unroll
            for (int mi = 0; mi < 4; mi++)
                ldsm4(a[mi], aA + (uint32_t)(mi * 16 * 36) * 4 + ko);
            ldsm4(b, aB + ko);
            #pragma unroll
            for (int mi = 0; mi < 4; mi++)
                #pragma unroll
                for (int ni = 0; ni < 2; ni++)
                    mma8(acc[mi][ni], a[mi][0], a[mi][1], a[mi][2], a[mi][3],
                         b[ni], b[2 + ni]);
        }
    }

    #pragma unroll
    for (int mi = 0; mi < 4; mi++) {
        int r0 = row0 + wm * 64 + mi * 16 + g;
        #pragma unroll
        for (int ni = 0; ni < 2; ni++) {
            int c = col0 + wn * 16 + ni * 8 + 2 * tg;
            float b0 = bias[c], b1 = bias[c + 1];
            *reinterpret_cast<float2*>(&out[(size_t)r0       * EMB + c]) =
                make_float2(acc[mi][ni][0] + b0, acc[mi][ni][1] + b1);
            *reinterpret_cast<float2*>(&out[(size_t)(r0 + 8) * EMB + c]) =
                make_float2(acc[mi][ni][2] + b0, acc[mi][ni][3] + b1);
        }
    }
}

// ===========================================================================
// Fused attention v2, 512 threads.
// QK tf32 (as R8). Softmax: max pass, sum pass (no store), final pass writes
// fp32 probs to gmem + normalized bf16 P to smem. PV bf16 with k-split warps.
// smem: S fp32 32x1036 | region2: [K 2x128x68 fp32] aliased with [P bf16
// 32x1048], then V bf16 2x64x72 after K buffers. Total 220672 B.
// ===========================================================================
#define SSTR 1036
#define KST  68
#define PSTB 1048
#define VSTB 72

__device__ __forceinline__ void issue_k(const float* __restrict__ gp,
                                        float* buf, int s, int t)
{
    #pragma unroll
    for (int i = 0; i < 4; i++) {
        int idx = t + i * 512;
        int r = idx >> 4, c4 = (idx & 15) * 4;
        cp16(smaddr(buf + r * KST + c4), gp + (size_t)(s * 128 + r) * FQKV + c4);
    }
    asm volatile("cp.async.commit_group;" ::: "memory");
}

__device__ __forceinline__ void issue_v(const __nv_bfloat16* __restrict__ gv,
                                        __nv_bfloat16* buf, int s, int t)
{
    int r = t >> 3, seg = t & 7;
    cp16(smaddr(buf + r * VSTB + seg * 8),
         gv + (size_t)(s * 64 + r) * EMB + seg * 8);
    asm volatile("cp.async.commit_group;" ::: "memory");
}

__global__ void __launch_bounds__(512) k_attn(float* __restrict__ attn)
{
    extern __shared__ float sm[];
    float* S  = sm;
    float* T0 = sm + 32 * SSTR;
    float* T1 = T0 + 128 * KST;
    __nv_bfloat16* Pb = (__nv_bfloat16*)(sm + 32 * SSTR);
    __nv_bfloat16* V0 = (__nv_bfloat16*)(T1 + 128 * KST);
    __nv_bfloat16* V1 = V0 + 64 * VSTB;

    const int bh = blockIdx.y;
    const int bb = bh / NHEAD, h = bh % NHEAD;
    const int row0 = blockIdx.x * 32;
    const int t = threadIdx.x, warp = t >> 5, lane = t & 31;
    const int g = lane >> 2, tg = lane & 3;
    const int lr = lane & 15, lc = (lane >> 4) << 2;

    const float* Qg = g_qkv + ((size_t)bb * SEQ + row0) * FQKV + h * HDIM;
    const float* Kg = g_qkv + (size_t)bb * SEQ * FQKV + EMB + h * HDIM;
    const __nv_bfloat16* Vg = g_vh + (size_t)bb * SEQ * EMB + h * HDIM;
    float* Sg = attn + ((size_t)bh * SEQ + row0) * SEQ;

    // ---- stage Q, pin tf32 fragments (QK warp layout: wm=warp>>3, wn=warp&7)
    const int qwm = warp >> 3, qwn = warp & 7;
    {
        int r = t >> 4, c4 = (t & 15) * 4;
        float4 v = *reinterpret_cast<const float4*>(&Qg[(size_t)r * FQKV + c4]);
        S[r * KST + c4 + 0] = v.x; S[r * KST + c4 + 1] = v.y;
        S[r * KST + c4 + 2] = v.z; S[r * KST + c4 + 3] = v.w;
    }
    __syncthreads();
    uint32_t qf[8][4];
    {
        const int rb = qwm * 16;
        #pragma unroll
        for (int ks = 0; ks < 8; ks++) {
            int kb = ks * 8;
            qf[ks][0] = f2tf(S[(rb + g    ) * KST + kb + tg]);
            qf[ks][1] = f2tf(S[(rb + g + 8) * KST + kb + tg]);
            qf[ks][2] = f2tf(S[(rb + g    ) * KST + kb + tg + 4]);
            qf[ks][3] = f2tf(S[(rb + g + 8) * KST + kb + tg + 4]);
        }
    }

    // ---- QK^T ----
    issue_k(Kg, T0, 0, t);
    const uint32_t kfragoff = (uint32_t)((qwn * 16 + lr) * KST + lc) * 4;

    for (int s = 0; s < 8; s++) {
        if (s < 7) {
            issue_k(Kg, (s & 1) ? T0 : T1, s + 1, t);
            asm volatile("cp.async.wait_group 1;" ::: "memory");
        } else {
            asm volatile("cp.async.wait_group 0;" ::: "memory");
        }
        __syncthreads();
        const float* Kb = (s & 1) ? T1 : T0;
        const uint32_t kbase = smaddr(Kb) + kfragoff;

        float acc[2][4] = {};
        #pragma unroll
        for (int ks = 0; ks < 8; ks++) {
            uint32_t b[4];
            ldsm4(b, kbase + (uint32_t)(ks * 8) * 4);
            mma8(acc[0], qf[ks][0], qf[ks][1], qf[ks][2], qf[ks][3], b[0], b[2]);
            mma8(acc[1], qf[ks][0], qf[ks][1], qf[ks][2], qf[ks][3], b[1], b[3]);
        }
        {
            int r = qwm * 16 + g;
            #pragma unroll
            for (int ni = 0; ni < 2; ni++) {
                int c = s * 128 + qwn * 16 + ni * 8 + 2 * tg;
                S[(size_t)r       * SSTR + c]     = acc[ni][0] * 0.125f;
                S[(size_t)r       * SSTR + c + 1] = acc[ni][1] * 0.125f;
                S[(size_t)(r + 8) * SSTR + c]     = acc[ni][2] * 0.125f;
                S[(size_t)(r + 8) * SSTR + c + 1] = acc[ni][3] * 0.125f;
            }
        }
        __syncthreads();
    }

    issue_v(Vg, V0, 0, t);   // prefetch V strip 0 under softmax

    // ---- softmax: 16 warps x 2 rows; no E store; write probs + bf16 P ----
    #pragma unroll
    for (int j = 0; j < 2; j++) {
        int r = warp * 2 + j;
        float* Sr = S + (size_t)r * SSTR;

        float m = -1e30f;
        #pragma unroll
        for (int it = 0; it < 8; it++) {
            float4 v = *reinterpret_cast<float4*>(&Sr[(it * 32 + lane) * 4]);
            m = fmaxf(m, fmaxf(fmaxf(v.x, v.y), fmaxf(v.z, v.w)));
        }
        #pragma unroll
        for (int o = 16; o > 0; o >>= 1) m = fmaxf(m, __shfl_xor_sync(0xffffffffu, m, o));

        float sum = 0.0f;
        #pragma unroll
        for (int it = 0; it < 8; it++) {
            float4 v = *reinterpret_cast<float4*>(&Sr[(it * 32 + lane) * 4]);
            sum += __expf(v.x - m) + __expf(v.y - m) + __expf(v.z - m) + __expf(v.w - m);
        }
        #pragma unroll
        for (int o = 16; o > 0; o >>= 1) sum += __shfl_xor_sync(0xffffffffu, sum, o);
        float inv = 1.0f / sum;

        float* arow = Sg + (size_t)r * SEQ;
        __nv_bfloat16* prow = Pb + (size_t)r * PSTB;
        #pragma unroll
        for (int it = 0; it < 8; it++) {
            int c = (it * 32 + lane) * 4;
            float4 v = *reinterpret_cast<float4*>(&Sr[c]);
            v.x = __expf(v.x - m) * inv; v.y = __expf(v.y - m) * inv;
            v.z = __expf(v.z - m) * inv; v.w = __expf(v.w - m) * inv;
            *reinterpret_cast<float4*>(&arow[c]) = v;
            __nv_bfloat162 p0 = __floats2bfloat162_rn(v.x, v.y);
            __nv_bfloat162 p1 = __floats2bfloat162_rn(v.z, v.w);
            uint2 u;
            u.x = *reinterpret_cast<uint32_t*>(&p0);
            u.y = *reinterpret_cast<uint32_t*>(&p1);
            *reinterpret_cast<uint2*>(&prow[c]) = u;
        }
    }

    // ---- PV bf16: warps = wm2 x wn2 x wk4; 16 strips of 64 k ----
    const int pwm = warp >> 3;            // 0..1
    const int pwk = (warp >> 1) & 3;      // 0..3
    const int pwn = warp & 1;             // 0..1
    const uint32_t aPbase = smaddr(Pb) +
        (uint32_t)((pwm * 16 + lr) * PSTB + (lane >> 4) * 8) * 2;
    float acc2[4][4] = {};

    for (int s = 0; s < 16; s++) {
        if (s < 15) {
            issue_v(Vg, (s & 1) ? V0 : V1, s + 1, t);
            asm volatile("cp.async.wait_group 1;" ::: "memory");
        } else {
            asm volatile("cp.async.wait_group 0;" ::: "memory");
        }
        __syncthreads();
        const __nv_bfloat16* Vb = (s & 1) ? V1 : V0;

        uint32_t aP[4];
        ldsm4(aP, aPbase + (uint32_t)(s * 64 + pwk * 16) * 2);
        const uint32_t vrow = smaddr(Vb) + (uint32_t)((pwk * 16 + lr) * VSTB) * 2;
        #pragma unroll
        for (int nt = 0; nt < 4; nt++) {
            uint32_t b0, b1;
            ldsm2t(b0, b1, vrow + (uint32_t)((pwn * 4 + nt) * 8) * 2);
            mma16(acc2[nt], aP, b0, b1);
        }
        __syncthreads();
    }

    // ---- reduce partials over wk (reuse S region) ----
    {
        float* R = S + (size_t)pwk * (32 * 64);
        int rbase = pwm * 16 + g;
        #pragma unroll
        for (int nt = 0; nt < 4; nt++) {
            int c = (pwn * 4 + nt) * 8 + 2 * tg;
            *reinterpret_cast<float2*>(&R[(size_t)rbase       * 64 + c]) =
                make_float2(acc2[nt][0], acc2[nt][1]);
            *reinterpret_cast<float2*>(&R[(size_t)(rbase + 8) * 64 + c]) =
                make_float2(acc2[nt][2], acc2[nt][3]);
        }
    }
    __syncthreads();
    {
        int row = t >> 4, c4 = (t & 15) * 4;
        float4 o = *reinterpret_cast<float4*>(&S[(size_t)row * 64 + c4]);
        #pragma unroll
        for (int k = 1; k < 4; k++) {
            float4 p = *reinterpret_cast<float4*>(&S[(size_t)(k * 2048 + row * 64 + c4)]);
            o.x += p.x; o.y += p.y; o.z += p.z; o.w += p.w;
        }
        *reinterpret_cast<float4*>(
            &g_oh[((size_t)bb * SEQ + row0 + row) * EMB + h * HDIM + c4]) = o;
    }
}

// ---------------------------------------------------------------------------
extern "C" void kernel_launch(void* const* d_in, const int* in_sizes, int n_in,
                              void* d_out, int out_size)
{
    const float* x     = (const float*)d_in[0];
    const float* w_qkv = (const float*)d_in[1];
    const float* b_qkv = (const float*)d_in[2];
    const float* w_out = (const float*)d_in[3];
    const float* b_out = (const float*)d_in[4];

    float* out  = (float*)d_out;
    float* attn = out + (size_t)MTOT * EMB;

    const int smem_qkv  = 2 * QKV_STAGE * 4;                        // 81920
    const int smem_out  = (128 * 36 + 64 * 36) * 4;                 // 27648
    const int smem_attn = 32 * SSTR * 4 + 2 * 128 * KST * 4 + 2 * 64 * VSTB * 2; // 220672

    static bool attr_done = false;
    if (!attr_done) {
        cudaFuncSetAttribute(k_qkv,  cudaFuncAttributeMaxDynamicSharedMemorySize, smem_qkv);
        cudaFuncSetAttribute(k_out,  cudaFuncAttributeMaxDynamicSharedMemorySize, smem_out);
        cudaFuncSetAttribute(k_attn, cudaFuncAttributeMaxDynamicSharedMemorySize, smem_attn);
        attr_done = true;
    }

    __nv_bfloat16 *xh, *xl, *wh, *wl;
    cudaGetSymbolAddress((void**)&xh, g_xh);
    cudaGetSymbolAddress((void**)&xl, g_xl);
    cudaGetSymbolAddress((void**)&wh, g_wh);
    cudaGetSymbolAddress((void**)&wl, g_wl);

    const int nx4 = MTOT * EMB / 4;
    const int nw4 = FQKV * EMB / 4;

    k_split<<<(nx4 + 255) / 256, 256>>>(x,     xh, xl, nx4);
    k_split<<<(nw4 + 255) / 256, 256>>>(w_qkv, wh, wl, nw4);

    k_qkv <<<dim3(FQKV / 128, MTOT / 128), 256, smem_qkv >>>(b_qkv);
    k_attn<<<dim3(SEQ / 32, BHTOT),        512, smem_attn>>>(attn);
    k_out <<<dim3(EMB / 64, MTOT / 128),   256, smem_out >>>(w_out, b_out, out);
}

// round 10
// speedup vs baseline: 1.0610x; 1.0069x over previous
#include <cuda_runtime.h>
#include <cuda_bf16.h>
#include <math.h>
#include <stdint.h>

#define EMB   768
#define NHEAD 12
#define HDIM  64
#define SEQ   1024
#define BATCH 8
#define MTOT  (BATCH * SEQ)
#define FQKV  (3 * EMB)
#define BHTOT (BATCH * NHEAD)

__device__ float g_qkv[(size_t)MTOT * FQKV];
__device__ float g_oh [(size_t)MTOT * EMB];
__device__ __nv_bfloat16 g_vh[(size_t)MTOT * EMB];
__device__ __nv_bfloat16 g_vl[(size_t)MTOT * EMB];
__device__ __nv_bfloat16 g_xh[(size_t)MTOT * EMB];
__device__ __nv_bfloat16 g_xl[(size_t)MTOT * EMB];
__device__ __nv_bfloat16 g_wh[(size_t)FQKV * EMB];
__device__ __nv_bfloat16 g_wl[(size_t)FQKV * EMB];

__device__ __forceinline__ uint32_t f2tf(float x) {
    uint32_t r;
    asm("cvt.rna.tf32.f32 %0, %1;" : "=r"(r) : "f"(x));
    return r;
}
__device__ __forceinline__ uint32_t smaddr(const void* p) {
    return (uint32_t)__cvta_generic_to_shared(p);
}
__device__ __forceinline__ void ldsm4(uint32_t* r, uint32_t a) {
    asm volatile("ldmatrix.sync.aligned.m8n8.x4.shared.b16 {%0,%1,%2,%3}, [%4];"
                 : "=r"(r[0]), "=r"(r[1]), "=r"(r[2]), "=r"(r[3]) : "r"(a));
}
__device__ __forceinline__ void ldsm2t(uint32_t& r0, uint32_t& r1, uint32_t a) {
    asm volatile("ldmatrix.sync.aligned.m8n8.x2.trans.shared.b16 {%0,%1}, [%2];"
                 : "=r"(r0), "=r"(r1) : "r"(a));
}
__device__ __forceinline__ void cp16(uint32_t dst, const void* src) {
    asm volatile("cp.async.cg.shared.global [%0], [%1], 16;" :: "r"(dst), "l"(src));
}
#define CP_COMMIT() asm volatile("cp.async.commit_group;" ::: "memory")

__device__ __forceinline__ void mma8(float* c,
                                     uint32_t a0, uint32_t a1, uint32_t a2, uint32_t a3,
                                     uint32_t b0, uint32_t b1)
{
    asm volatile(
        "mma.sync.aligned.m16n8k8.row.col.f32.tf32.tf32.f32 "
        "{%0,%1,%2,%3}, {%4,%5,%6,%7}, {%8,%9}, {%0,%1,%2,%3};\n"
        : "+f"(c[0]), "+f"(c[1]), "+f"(c[2]), "+f"(c[3])
        : "r"(a0), "r"(a1), "r"(a2), "r"(a3), "r"(b0), "r"(b1));
}
__device__ __forceinline__ void mma16(float* c, const uint32_t* a,
                                      uint32_t b0, uint32_t b1)
{
    asm volatile(
        "mma.sync.aligned.m16n8k16.row.col.f32.bf16.bf16.f32 "
        "{%0,%1,%2,%3}, {%4,%5,%6,%7}, {%8,%9}, {%0,%1,%2,%3};\n"
        : "+f"(c[0]), "+f"(c[1]), "+f"(c[2]), "+f"(c[3])
        : "r"(a[0]), "r"(a[1]), "r"(a[2]), "r"(a[3]), "r"(b0), "r"(b1));
}

__device__ __forceinline__ void packhl(float x, float y, uint32_t& hi, uint32_t& lo)
{
    __nv_bfloat162 h = __floats2bfloat162_rn(x, y);
    hi = *reinterpret_cast<uint32_t*>(&h);
    __nv_bfloat162 l = __floats2bfloat162_rn(x - __bfloat162float(h.x),
                                             y - __bfloat162float(h.y));
    lo = *reinterpret_cast<uint32_t*>(&l);
}

// ===========================================================================
// Pre-split x / w_qkv to bf16 hi/lo
// ===========================================================================
__global__ void __launch_bounds__(256) k_split(const float* __restrict__ src,
                                               __nv_bfloat16* __restrict__ hi,
                                               __nv_bfloat16* __restrict__ lo,
                                               int n4)
{
    int i = blockIdx.x * blockDim.x + threadIdx.x;
    if (i >= n4) return;
    float4 v = reinterpret_cast<const float4*>(src)[i];
    uint32_t h0, l0, h1, l1;
    packhl(v.x, v.y, h0, l0);
    packhl(v.z, v.w, h1, l1);
    reinterpret_cast<uint32_t*>(hi)[i * 2]     = h0;
    reinterpret_cast<uint32_t*>(hi)[i * 2 + 1] = h1;
    reinterpret_cast<uint32_t*>(lo)[i * 2]     = l0;
    reinterpret_cast<uint32_t*>(lo)[i * 2 + 1] = l1;
}

// ===========================================================================
// QKV projection (as R8) + bf16 hi/lo V side-copy in epilogue
// ===========================================================================
#define PSTR 20
#define QKV_STAGE (4 * 128 * PSTR)

__device__ __forceinline__ void qkv_issue(uint32_t base, int row0, int col0,
                                          int k0, int t)
{
    #pragma unroll
    for (int i = 0; i < 2; i++) {
        int idx = t + i * 256;
        int r = idx >> 2, seg = idx & 3;
        uint32_t dst = base + (uint32_t)(r * PSTR + seg * 4) * 4;
        size_t so = (size_t)(row0 + r) * EMB + k0 + seg * 8;
        cp16(dst,                  g_xh + so);
        cp16(dst + 128 * PSTR * 4, g_xl + so);
    }
    #pragma unroll
    for (int i = 0; i < 2; i++) {
        int idx = t + i * 256;
        int r = idx >> 2, seg = idx & 3;
        uint32_t dst = base + (uint32_t)(2 * 128 * PSTR + r * PSTR + seg * 4) * 4;
        size_t so = (size_t)(col0 + r) * EMB + k0 + seg * 8;
        cp16(dst,                  g_wh + so);
        cp16(dst + 128 * PSTR * 4, g_wl + so);
    }
    CP_COMMIT();
}

__global__ void __launch_bounds__(256, 2) k_qkv(const float* __restrict__ bias)
{
    extern __shared__ uint32_t smu[];

    const int row0 = blockIdx.y * 128, col0 = blockIdx.x * 128;
    const int t = threadIdx.x, warp = t >> 5, lane = t & 31;
    const int wm = warp >> 2, wn = warp & 3;
    const int g = lane >> 2, tg = lane & 3;
    const int lr = lane & 15, lc = (lane >> 4) << 2;

    const uint32_t sbase = smaddr(smu);
    float acc[4][4][4] = {};

    qkv_issue(sbase, row0, col0, 0, t);

    for (int s = 0; s < 24; s++) {
        if (s < 23) {
            qkv_issue(sbase + ((s + 1) & 1) * (QKV_STAGE * 4), row0, col0,
                      (s + 1) * 32, t);
            asm volatile("cp.async.wait_group 1;" ::: "memory");
        } else {
            asm volatile("cp.async.wait_group 0;" ::: "memory");
        }
        __syncthreads();

        const uint32_t sb  = sbase + (s & 1) * (QKV_STAGE * 4);
        const uint32_t aAh = sb + (uint32_t)((wm * 64 + lr) * PSTR + lc) * 4;
        const uint32_t aAl = aAh + 128 * PSTR * 4;
        const uint32_t aBh = sb + (uint32_t)(2 * 128 * PSTR + (wn * 32 + lr) * PSTR + lc) * 4;
        const uint32_t aBl = aBh + 128 * PSTR * 4;

        #pragma unroll
        for (int ks = 0; ks < 2; ks++) {
            const uint32_t po = (uint32_t)(ks * 8) * 4;
            uint32_t bh[2][4], bl[2][4];
            #pragma unroll
            for (int j = 0; j < 2; j++) {
                ldsm4(bh[j], aBh + (uint32_t)(j * 16 * PSTR) * 4 + po);
                ldsm4(bl[j], aBl + (uint32_t)(j * 16 * PSTR) * 4 + po);
            }
            #pragma unroll
            for (int mi = 0; mi < 4; mi++) {
                uint32_t ah[4], al[4];
                ldsm4(ah, aAh + (uint32_t)(mi * 16 * PSTR) * 4 + po);
                ldsm4(al, aAl + (uint32_t)(mi * 16 * PSTR) * 4 + po);
                #pragma unroll
                for (int j = 0; j < 2; j++)
                    #pragma unroll
                    for (int ni = 0; ni < 2; ni++) {
                        float* c = acc[mi][j * 2 + ni];
                        mma16(c, ah, bh[j][ni], bh[j][2 + ni]);
                        mma16(c, ah, bl[j][ni], bl[j][2 + ni]);
                        mma16(c, al, bh[j][ni], bh[j][2 + ni]);
                    }
            }
        }
        __syncthreads();
    }

    const bool isV = (col0 >= 2 * EMB);
    #pragma unroll
    for (int mi = 0; mi < 4; mi++) {
        int r0 = row0 + wm * 64 + mi * 16 + g;
        #pragma unroll
        for (int q = 0; q < 4; q++) {
            int c = col0 + wn * 32 + q * 8 + 2 * tg;
            float b0 = bias[c], b1 = bias[c + 1];
            float v00 = acc[mi][q][0] + b0, v01 = acc[mi][q][1] + b1;
            float v10 = acc[mi][q][2] + b0, v11 = acc[mi][q][3] + b1;
            *reinterpret_cast<float2*>(&g_qkv[(size_t)r0       * FQKV + c]) = make_float2(v00, v01);
            *reinterpret_cast<float2*>(&g_qkv[(size_t)(r0 + 8) * FQKV + c]) = make_float2(v10, v11);
            if (isV) {
                int cv = c - 2 * EMB;
                uint32_t h0, l0, h1, l1;
                packhl(v00, v01, h0, l0);
                packhl(v10, v11, h1, l1);
                *reinterpret_cast<uint32_t*>(&g_vh[(size_t)r0       * EMB + cv]) = h0;
                *reinterpret_cast<uint32_t*>(&g_vl[(size_t)r0       * EMB + cv]) = l0;
                *reinterpret_cast<uint32_t*>(&g_vh[(size_t)(r0 + 8) * EMB + cv]) = h1;
                *reinterpret_cast<uint32_t*>(&g_vl[(size_t)(r0 + 8) * EMB + cv]) = l1;
            }
        }
    }
}

// ===========================================================================
// Output projection (unchanged)
// ===========================================================================
__global__ void __launch_bounds__(256) k_out(const float* __restrict__ w,
                                             const float* __restrict__ bias,
                                             float* __restrict__ out)
{
    extern __shared__ uint32_t smo[];
    uint32_t* Ah = smo;
    uint32_t* Bh = Ah + 128 * 36;

    const int row0 = blockIdx.y * 128, col0 = blockIdx.x * 64;
    const int t = threadIdx.x, warp = t >> 5, lane = t & 31;
    const int wm = warp >> 2, wn = warp & 3;
    const int g = lane >> 2, tg = lane & 3;
    const int lr = lane & 15, lc = (lane >> 4) << 2;

    const uint32_t aA = smaddr(Ah) + (uint32_t)((wm * 64 + lr) * 36 + lc) * 4;
    const uint32_t aB = smaddr(Bh) + (uint32_t)((wn * 16 + lr) * 36 + lc) * 4;

    float acc[4][2][4] = {};
    float4 pa[4], pb[2];

    #pragma unroll
    for (int i = 0; i < 4; i++) {
        int idx = t + i * 256;
        int r = idx >> 3, c4 = (idx & 7) * 4;
        pa[i] = *reinterpret_cast<const float4*>(&g_oh[(size_t)(row0 + r) * EMB + c4]);
    }
    #pragma unroll
    for (int i = 0; i < 2; i++) {
        int idx = t + i * 256;
        int r = idx >> 3, c4 = (idx & 7) * 4;
        pb[i] = *reinterpret_cast<const float4*>(&w[(size_t)(col0 + r) * EMB + c4]);
    }

    for (int k0 = 0; k0 < EMB; k0 += 32) {
        __syncthreads();
        #pragma unroll
        for (int i = 0; i < 4; i++) {
            int idx = t + i * 256;
            int r = idx >> 3, c4 = (idx & 7) * 4;
            Ah[r * 36 + c4 + 0] = f2tf(pa[i].x); Ah[r * 36 + c4 + 1] = f2tf(pa[i].y);
            Ah[r * 36 + c4 + 2] = f2tf(pa[i].z); Ah[r * 36 + c4 + 3] = f2tf(pa[i].w);
        }
        #pragma unroll
        for (int i = 0; i < 2; i++) {
            int idx = t + i * 256;
            int r = idx >> 3, c4 = (idx & 7) * 4;
            Bh[r * 36 + c4 + 0] = f2tf(pb[i].x); Bh[r * 36 + c4 + 1] = f2tf(pb[i].y);
            Bh[r * 36 + c4 + 2] = f2tf(pb[i].z); Bh[r * 36 + c4 + 3] = f2tf(pb[i].w);
        }
        __syncthreads();

        int kn = k0 + 32;
        if (kn < EMB) {
            #pragma unroll
            for (int i = 0; i < 4; i++) {
                int idx = t + i * 256;
                int r = idx >> 3, c4 = (idx & 7) * 4;
                pa[i] = *reinterpret_cast<const float4*>(&g_oh[(size_t)(row0 + r) * EMB + kn + c4]);
            }
            #pragma unroll
            for (int i = 0; i < 2; i++) {
                int idx = t + i * 256;
                int r = idx >> 3, c4 = (idx & 7) * 4;
                pb[i] = *reinterpret_cast<const float4*>(&w[(size_t)(col0 + r) * EMB + kn + c4]);
            }
        }

        #pragma unroll
        for (int ks = 0; ks < 4; ks++) {
            const uint32_t ko = (uint32_t)(ks * 8) * 4;
            uint32_t a[4][4], b[4];
            #pragma unroll
            for (int mi = 0; mi < 4; mi++)
                ldsm4(a[mi], aA + (uint32_t)(mi * 16 * 36) * 4 + ko);
            ldsm4(b, aB + ko);
            #pragma unroll
            for (int mi = 0; mi < 4; mi++)
                #pragma unroll
                for (int ni = 0; ni < 2; ni++)
                    mma8(acc[mi][ni], a[mi][0], a[mi][1], a[mi][2], a[mi][3],
                         b[ni], b[2 + ni]);
        }
    }

    #pragma unroll
    for (int mi = 0; mi < 4; mi++) {
        int r0 = row0 + wm * 64 + mi * 16 + g;
        #pragma unroll
        for (int ni = 0; ni < 2; ni++) {
            int c = col0 + wn * 16 + ni * 8 + 2 * tg;
            float b0 = bias[c], b1 = bias[c + 1];
            *reinterpret_cast<float2*>(&out[(size_t)r0       * EMB + c]) =
                make_float2(acc[mi][ni][0] + b0, acc[mi][ni][1] + b1);
            *reinterpret_cast<float2*>(&out[(size_t)(r0 + 8) * EMB + c]) =
                make_float2(acc[mi][ni][2] + b0, acc[mi][ni][3] + b1);
        }
    }
}

// ===========================================================================
// Fused attention v3: two-pass register-resident flash attention.
// CTA = 64 q rows, 512 threads, warps 4m x 4n. Strips of 64 keys, ring-4.
// Pass A: QK tf32 -> online (m,l) in regs. Merge. Pass B: recompute QK,
// write probs once, PV in split-bf16 straight from accumulator repack.
// ===========================================================================
#define RT    64
#define KST2  68
#define VST2  72
#define KBUF_F (64 * KST2)
#define VBUF_E (64 * VST2)
// smem bytes: K 4*KBUF_F*4 = 69632 | Vh 4*VBUF_E*2 = 36864 | Vl 36864
//           | mscr 4*64*2*4 = 2048 | fscr 64*2*4 = 512  => 145920
#define SMO_VH 69632
#define SMO_VL (69632 + 36864)
#define SMO_MS (69632 + 2 * 36864)
#define SMO_FS (SMO_MS + 2048)
#define SM_ATTN_BYTES (SMO_FS + 512)

__device__ __forceinline__ void attn_issue_k(char* smc, const float* __restrict__ Kg,
                                             int s, int t)
{
    float* kb = (float*)smc + (size_t)(s & 3) * KBUF_F;
    #pragma unroll
    for (int i = 0; i < 2; i++) {
        int idx = t + i * 512;
        int r = idx >> 4, c4 = (idx & 15) * 4;
        cp16(smaddr(kb + r * KST2 + c4), Kg + (size_t)(s * 64 + r) * FQKV + c4);
    }
}

__device__ __forceinline__ void attn_issue_v(char* smc,
                                             const __nv_bfloat16* __restrict__ VgH,
                                             const __nv_bfloat16* __restrict__ VgL,
                                             int s, int t)
{
    __nv_bfloat16* vh = (__nv_bfloat16*)(smc + SMO_VH) + (size_t)(s & 3) * VBUF_E;
    __nv_bfloat16* vl = (__nv_bfloat16*)(smc + SMO_VL) + (size_t)(s & 3) * VBUF_E;
    int r = t >> 3, seg = t & 7;
    size_t go = (size_t)(s * 64 + r) * EMB + seg * 8;
    cp16(smaddr(vh + r * VST2 + seg * 8), VgH + go);
    cp16(smaddr(vl + r * VST2 + seg * 8), VgL + go);
}

__global__ void __launch_bounds__(512) k_attn(float* __restrict__ attn)
{
    extern __shared__ char smc[];
    float* Kb   = (float*)smc;
    float* mscr = (float*)(smc + SMO_MS);
    float* fscr = (float*)(smc + SMO_FS);

    const int bh = blockIdx.y;
    const int bb = bh / NHEAD, h = bh % NHEAD;
    const int row0 = blockIdx.x * RT;
    const int t = threadIdx.x, warp = t >> 5, lane = t & 31;
    const int g = lane >> 2, tg = lane & 3;
    const int wm = warp >> 2, wn = warp & 3;
    const int lr = lane & 15, lc = (lane >> 4) << 2;

    const float* Qg = g_qkv + ((size_t)bb * SEQ + row0) * FQKV + h * HDIM;
    const float* Kg = g_qkv + (size_t)bb * SEQ * FQKV + EMB + h * HDIM;
    const __nv_bfloat16* VgH = g_vh + (size_t)bb * SEQ * EMB + h * HDIM;
    const __nv_bfloat16* VgL = g_vl + (size_t)bb * SEQ * EMB + h * HDIM;

    // ---- stage Q (64x64) in Kb[0..], pin tf32 fragments ----
    #pragma unroll
    for (int i = 0; i < 2; i++) {
        int idx = t + i * 512;
        int r = idx >> 4, c4 = (idx & 15) * 4;
        float4 v = *reinterpret_cast<const float4*>(&Qg[(size_t)r * FQKV + c4]);
        Kb[r * KST2 + c4 + 0] = v.x; Kb[r * KST2 + c4 + 1] = v.y;
        Kb[r * KST2 + c4 + 2] = v.z; Kb[r * KST2 + c4 + 3] = v.w;
    }
    __syncthreads();
    uint32_t qf[8][4];
    {
        const int rb = wm * 16;
        #pragma unroll
        for (int ks = 0; ks < 8; ks++) {
            int kb = ks * 8;
            qf[ks][0] = f2tf(Kb[(rb + g    ) * KST2 + kb + tg]);
            qf[ks][1] = f2tf(Kb[(rb + g + 8) * KST2 + kb + tg]);
            qf[ks][2] = f2tf(Kb[(rb + g    ) * KST2 + kb + tg + 4]);
            qf[ks][3] = f2tf(Kb[(rb + g + 8) * KST2 + kb + tg + 4]);
        }
    }
    __syncthreads();

    const uint32_t kfrag = (uint32_t)((wn * 16 + lr) * KST2 + lc) * 4;
    const float sc = 0.125f;

    // ================= PASS A: online (m,l), no S storage =================
    attn_issue_k(smc, Kg, 0, t); CP_COMMIT();
    attn_issue_k(smc, Kg, 1, t); CP_COMMIT();

    float m0 = -1e30f, l0 = 0.0f, m1 = -1e30f, l1 = 0.0f;

    for (int s = 0; s < 16; s++) {
        if (s < 14) {
            attn_issue_k(smc, Kg, s + 2, t); CP_COMMIT();
            asm volatile("cp.async.wait_group 2;" ::: "memory");
        } else if (s == 14) {
            asm volatile("cp.async.wait_group 1;" ::: "memory");
        } else {
            asm volatile("cp.async.wait_group 0;" ::: "memory");
        }
        __syncthreads();
        const uint32_t kbase = smaddr((float*)smc + (size_t)(s & 3) * KBUF_F) + kfrag;

        float acc[2][4] = {};
        #pragma unroll
        for (int ks = 0; ks < 8; ks++) {
            uint32_t b[4];
            ldsm4(b, kbase + (uint32_t)(ks * 8) * 4);
            mma8(acc[0], qf[ks][0], qf[ks][1], qf[ks][2], qf[ks][3], b[0], b[2]);
            mma8(acc[1], qf[ks][0], qf[ks][1], qf[ks][2], qf[ks][3], b[1], b[3]);
        }
        {
            float v0 = acc[0][0] * sc, v1 = acc[0][1] * sc,
                  v2 = acc[1][0] * sc, v3 = acc[1][1] * sc;
            float mx = fmaxf(fmaxf(v0, v1), fmaxf(v2, v3));
            float mn = fmaxf(m0, mx);
            l0 = l0 * __expf(m0 - mn) + __expf(v0 - mn) + __expf(v1 - mn)
                                      + __expf(v2 - mn) + __expf(v3 - mn);
            m0 = mn;
        }
        {
            float v0 = acc[0][2] * sc, v1 = acc[0][3] * sc,
                  v2 = acc[1][2] * sc, v3 = acc[1][3] * sc;
            float mx = fmaxf(fmaxf(v0, v1), fmaxf(v2, v3));
            float mn = fmaxf(m1, mx);
            l1 = l1 * __expf(m1 - mn) + __expf(v0 - mn) + __expf(v1 - mn)
                                      + __expf(v2 - mn) + __expf(v3 - mn);
            m1 = mn;
        }
    }

    // prologue for pass B (safe: buffers 0,1 long retired)
    attn_issue_k(smc, Kg, 0, t); attn_issue_v(smc, VgH, VgL, 0, t); CP_COMMIT();
    attn_issue_k(smc, Kg, 1, t); attn_issue_v(smc, VgH, VgL, 1, t); CP_COMMIT();

    // ---- merge (m,l): lanes (tg) then warps (wn) ----
    #pragma unroll
    for (int off = 1; off <= 2; off <<= 1) {
        float mo = __shfl_xor_sync(0xffffffffu, m0, off);
        float lo = __shfl_xor_sync(0xffffffffu, l0, off);
        float mn = fmaxf(m0, mo);
        l0 = l0 * __expf(m0 - mn) + lo * __expf(mo - mn); m0 = mn;
        mo = __shfl_xor_sync(0xffffffffu, m1, off);
        lo = __shfl_xor_sync(0xffffffffu, l1, off);
        mn = fmaxf(m1, mo);
        l1 = l1 * __expf(m1 - mn) + lo * __expf(mo - mn); m1 = mn;
    }
    if (tg == 0) {
        mscr[(wn * 64 + wm * 16 + g    ) * 2]     = m0;
        mscr[(wn * 64 + wm * 16 + g    ) * 2 + 1] = l0;
        mscr[(wn * 64 + wm * 16 + g + 8) * 2]     = m1;
        mscr[(wn * 64 + wm * 16 + g + 8) * 2 + 1] = l1;
    }
    __syncthreads();
    if (t < 64) {
        float M = -1e30f, L = 0.0f;
        #pragma unroll
        for (int j = 0; j < 4; j++) {
            float mj = mscr[(j * 64 + t) * 2];
            float lj = mscr[(j * 64 + t) * 2 + 1];
            float mn = fmaxf(M, mj);
            L = L * __expf(M - mn) + lj * __expf(mj - mn);
            M = mn;
        }
        fscr[t * 2]     = M;
        fscr[t * 2 + 1] = 1.0f / L;
    }
    __syncthreads();
    const float mf0 = fscr[(wm * 16 + g    ) * 2];
    const float iv0 = fscr[(wm * 16 + g    ) * 2 + 1];
    const float mf1 = fscr[(wm * 16 + g + 8) * 2];
    const float iv1 = fscr[(wm * 16 + g + 8) * 2 + 1];

    // ================= PASS B: probs out + PV =================
    float O[8][4] = {};
    float* ar0 = attn + ((size_t)bh * SEQ + row0 + wm * 16 + g) * SEQ;
    float* ar1 = ar0 + 8 * SEQ;

    for (int s = 0; s < 16; s++) {
        if (s < 14) {
            attn_issue_k(smc, Kg, s + 2, t);
            attn_issue_v(smc, VgH, VgL, s + 2, t); CP_COMMIT();
            asm volatile("cp.async.wait_group 2;" ::: "memory");
        } else if (s == 14) {
            asm volatile("cp.async.wait_group 1;" ::: "memory");
        } else {
            asm volatile("cp.async.wait_group 0;" ::: "memory");
        }
        __syncthreads();
        const uint32_t kbase = smaddr((float*)smc + (size_t)(s & 3) * KBUF_F) + kfrag;

        float acc[2][4] = {};
        #pragma unroll
        for (int ks = 0; ks < 8; ks++) {
            uint32_t b[4];
            ldsm4(b, kbase + (uint32_t)(ks * 8) * 4);
            mma8(acc[0], qf[ks][0], qf[ks][1], qf[ks][2], qf[ks][3], b[0], b[2]);
            mma8(acc[1], qf[ks][0], qf[ks][1], qf[ks][2], qf[ks][3], b[1], b[3]);
        }

        float p00 = __expf(acc[0][0] * sc - mf0) * iv0;
        float p01 = __expf(acc[0][1] * sc - mf0) * iv0;
        float p02 = __expf(acc[1][0] * sc - mf0) * iv0;
        float p03 = __expf(acc[1][1] * sc - mf0) * iv0;
        float q00 = __expf(acc[0][2] * sc - mf1) * iv1;
        float q01 = __expf(acc[0][3] * sc - mf1) * iv1;
        float q02 = __expf(acc[1][2] * sc - mf1) * iv1;
        float q03 = __expf(acc[1][3] * sc - mf1) * iv1;

        int c = s * 64 + wn * 16 + 2 * tg;
        *reinterpret_cast<float2*>(&ar0[c])     = make_float2(p00, p01);
        *reinterpret_cast<float2*>(&ar0[c + 8]) = make_float2(p02, p03);
        *reinterpret_cast<float2*>(&ar1[c])     = make_float2(q00, q01);
        *reinterpret_cast<float2*>(&ar1[c + 8]) = make_float2(q02, q03);

        uint32_t ah[4], al[4];
        packhl(p00, p01, ah[0], al[0]);
        packhl(q00, q01, ah[1], al[1]);
        packhl(p02, p03, ah[2], al[2]);
        packhl(q02, q03, ah[3], al[3]);

        const uint32_t vrh = smaddr((__nv_bfloat16*)(smc + SMO_VH) +
                                    (size_t)(s & 3) * VBUF_E + (wn * 16 + lr) * VST2) * 1;
        const uint32_t vrl = smaddr((__nv_bfloat16*)(smc + SMO_VL) +
                                    (size_t)(s & 3) * VBUF_E + (wn * 16 + lr) * VST2) * 1;
        #pragma unroll
        for (int nt = 0; nt < 8; nt++) {
            uint32_t b0, b1, c0, c1;
            ldsm2t(b0, b1, vrh + (uint32_t)(nt * 8) * 2);
            ldsm2t(c0, c1, vrl + (uint32_t)(nt * 8) * 2);
            mma16(O[nt], ah, b0, b1);
            mma16(O[nt], al, b0, b1);
            mma16(O[nt], ah, c0, c1);
        }
    }

    // ---- reduce O over wn (reuse K/V smem region) ----
    __syncthreads();
    float* Ored = (float*)smc;
    if (wn > 0) {
        float* R = Ored + (size_t)((wn - 1) * 4 + wm) * 1024;
        #pragma unroll
        for (int nt = 0; nt < 8; nt++) {
            R[(g    ) * 64 + nt * 8 + 2 * tg]     = O[nt][0];
            R[(g    ) * 64 + nt * 8 + 2 * tg + 1] = O[nt][1];
            R[(g + 8) * 64 + nt * 8 + 2 * tg]     = O[nt][2];
            R[(g + 8) * 64 + nt * 8 + 2 * tg + 1] = O[nt][3];
        }
    }
    __syncthreads();
    if (wn == 0) {
        #pragma unroll
        for (int j = 0; j < 3; j++) {
            const float* R = Ored + (size_t)(j * 4 + wm) * 1024;
            #pragma unroll
            for (int nt = 0; nt < 8; nt++) {
                O[nt][0] += R[(g    ) * 64 + nt * 8 + 2 * tg];
                O[nt][1] += R[(g    ) * 64 + nt * 8 + 2 * tg + 1];
                O[nt][2] += R[(g + 8) * 64 + nt * 8 + 2 * tg];
                O[nt][3] += R[(g + 8) * 64 + nt * 8 + 2 * tg + 1];
            }
        }
        float* o0 = g_oh + ((size_t)bb * SEQ + row0 + wm * 16 + g) * EMB + h * HDIM;
        float* o1 = o0 + 8 * EMB;
        #pragma unroll
        for (int nt = 0; nt < 8; nt++) {
            *reinterpret_cast<float2*>(&o0[nt * 8 + 2 * tg]) = make_float2(O[nt][0], O[nt][1]);
            *reinterpret_cast<float2*>(&o1[nt * 8 + 2 * tg]) = make_float2(O[nt][2], O[nt][3]);
        }
    }
}

// ---------------------------------------------------------------------------
extern "C" void kernel_launch(void* const* d_in, const int* in_sizes, int n_in,
                              void* d_out, int out_size)
{
    const float* x     = (const float*)d_in[0];
    const float* w_qkv = (const float*)d_in[1];
    const float* b_qkv = (const float*)d_in[2];
    const float* w_out = (const float*)d_in[3];
    const float* b_out = (const float*)d_in[4];

    float* out  = (float*)d_out;
    float* attn = out + (size_t)MTOT * EMB;

    const int smem_qkv  = 2 * QKV_STAGE * 4;          // 81920
    const int smem_out  = (128 * 36 + 64 * 36) * 4;   // 27648
    const int smem_attn = SM_ATTN_BYTES;              // 145920

    static bool attr_done = false;
    if (!attr_done) {
        cudaFuncSetAttribute(k_qkv,  cudaFuncAttributeMaxDynamicSharedMemorySize, smem_qkv);
        cudaFuncSetAttribute(k_out,  cudaFuncAttributeMaxDynamicSharedMemorySize, smem_out);
        cudaFuncSetAttribute(k_attn, cudaFuncAttributeMaxDynamicSharedMemorySize, smem_attn);
        attr_done = true;
    }

    __nv_bfloat16 *xh, *xl, *wh, *wl;
    cudaGetSymbolAddress((void**)&xh, g_xh);
    cudaGetSymbolAddress((void**)&xl, g_xl);
    cudaGetSymbolAddress((void**)&wh, g_wh);
    cudaGetSymbolAddress((void**)&wl, g_wl);

    const int nx4 = MTOT * EMB / 4;
    const int nw4 = FQKV * EMB / 4;

    k_split<<<(nx4 + 255) / 256, 256>>>(x,     xh, xl, nx4);
    k_split<<<(nw4 + 255) / 256, 256>>>(w_qkv, wh, wl, nw4);

    k_qkv <<<dim3(FQKV / 128, MTOT / 128), 256, smem_qkv >>>(b_qkv);
    k_attn<<<dim3(SEQ / RT, BHTOT),        512, smem_attn>>>(attn);
    k_out <<<dim3(EMB / 64, MTOT / 128),   256, smem_out >>>(w_out, b_out, out);
}

// round 11
// speedup vs baseline: 1.1151x; 1.0511x over previous
#include <cuda_runtime.h>
#include <cuda_bf16.h>
#include <math.h>
#include <stdint.h>

#define EMB   768
#define NHEAD 12
#define HDIM  64
#define SEQ   1024
#define BATCH 8
#define MTOT  (BATCH * SEQ)
#define FQKV  (3 * EMB)
#define BHTOT (BATCH * NHEAD)

__device__ float g_qkv[(size_t)MTOT * FQKV];
__device__ float g_oh [(size_t)MTOT * EMB];
__device__ __nv_bfloat16 g_vh[(size_t)MTOT * EMB];
__device__ __nv_bfloat16 g_vl[(size_t)MTOT * EMB];
__device__ __nv_bfloat16 g_xh[(size_t)MTOT * EMB];
__device__ __nv_bfloat16 g_xl[(size_t)MTOT * EMB];
__device__ __nv_bfloat16 g_wh[(size_t)FQKV * EMB];
__device__ __nv_bfloat16 g_wl[(size_t)FQKV * EMB];

__device__ __forceinline__ uint32_t f2tf(float x) {
    uint32_t r;
    asm("cvt.rna.tf32.f32 %0, %1;" : "=r"(r) : "f"(x));
    return r;
}
__device__ __forceinline__ uint32_t smaddr(const void* p) {
    return (uint32_t)__cvta_generic_to_shared(p);
}
__device__ __forceinline__ void ldsm4(uint32_t* r, uint32_t a) {
    asm volatile("ldmatrix.sync.aligned.m8n8.x4.shared.b16 {%0,%1,%2,%3}, [%4];"
                 : "=r"(r[0]), "=r"(r[1]), "=r"(r[2]), "=r"(r[3]) : "r"(a));
}
__device__ __forceinline__ void ldsm2t(uint32_t& r0, uint32_t& r1, uint32_t a) {
    asm volatile("ldmatrix.sync.aligned.m8n8.x2.trans.shared.b16 {%0,%1}, [%2];"
                 : "=r"(r0), "=r"(r1) : "r"(a));
}
__device__ __forceinline__ void cp16(uint32_t dst, const void* src) {
    asm volatile("cp.async.cg.shared.global [%0], [%1], 16;" :: "r"(dst), "l"(src));
}
#define CP_COMMIT() asm volatile("cp.async.commit_group;" ::: "memory")

__device__ __forceinline__ void mma8(float* c,
                                     uint32_t a0, uint32_t a1, uint32_t a2, uint32_t a3,
                                     uint32_t b0, uint32_t b1)
{
    asm volatile(
        "mma.sync.aligned.m16n8k8.row.col.f32.tf32.tf32.f32 "
        "{%0,%1,%2,%3}, {%4,%5,%6,%7}, {%8,%9}, {%0,%1,%2,%3};\n"
        : "+f"(c[0]), "+f"(c[1]), "+f"(c[2]), "+f"(c[3])
        : "r"(a0), "r"(a1), "r"(a2), "r"(a3), "r"(b0), "r"(b1));
}
__device__ __forceinline__ void mma16(float* c, const uint32_t* a,
                                      uint32_t b0, uint32_t b1)
{
    asm volatile(
        "mma.sync.aligned.m16n8k16.row.col.f32.bf16.bf16.f32 "
        "{%0,%1,%2,%3}, {%4,%5,%6,%7}, {%8,%9}, {%0,%1,%2,%3};\n"
        : "+f"(c[0]), "+f"(c[1]), "+f"(c[2]), "+f"(c[3])
        : "r"(a[0]), "r"(a[1]), "r"(a[2]), "r"(a[3]), "r"(b0), "r"(b1));
}

__device__ __forceinline__ void packhl(float x, float y, uint32_t& hi, uint32_t& lo)
{
    __nv_bfloat162 h = __floats2bfloat162_rn(x, y);
    hi = *reinterpret_cast<uint32_t*>(&h);
    __nv_bfloat162 l = __floats2bfloat162_rn(x - __bfloat162float(h.x),
                                             y - __bfloat162float(h.y));
    lo = *reinterpret_cast<uint32_t*>(&l);
}

// ===========================================================================
// Pre-split x / w_qkv to bf16 hi/lo
// ===========================================================================
__global__ void __launch_bounds__(256) k_split(const float* __restrict__ src,
                                               __nv_bfloat16* __restrict__ hi,
                                               __nv_bfloat16* __restrict__ lo,
                                               int n4)
{
    int i = blockIdx.x * blockDim.x + threadIdx.x;
    if (i >= n4) return;
    float4 v = reinterpret_cast<const float4*>(src)[i];
    uint32_t h0, l0, h1, l1;
    packhl(v.x, v.y, h0, l0);
    packhl(v.z, v.w, h1, l1);
    reinterpret_cast<uint32_t*>(hi)[i * 2]     = h0;
    reinterpret_cast<uint32_t*>(hi)[i * 2 + 1] = h1;
    reinterpret_cast<uint32_t*>(lo)[i * 2]     = l0;
    reinterpret_cast<uint32_t*>(lo)[i * 2 + 1] = l1;
}

// ===========================================================================
// QKV projection (unchanged) + bf16 hi/lo V side-copy
// ===========================================================================
#define PSTR 20
#define QKV_STAGE (4 * 128 * PSTR)

__device__ __forceinline__ void qkv_issue(uint32_t base, int row0, int col0,
                                          int k0, int t)
{
    #pragma unroll
    for (int i = 0; i < 2; i++) {
        int idx = t + i * 256;
        int r = idx >> 2, seg = idx & 3;
        uint32_t dst = base + (uint32_t)(r * PSTR + seg * 4) * 4;
        size_t so = (size_t)(row0 + r) * EMB + k0 + seg * 8;
        cp16(dst,                  g_xh + so);
        cp16(dst + 128 * PSTR * 4, g_xl + so);
    }
    #pragma unroll
    for (int i = 0; i < 2; i++) {
        int idx = t + i * 256;
        int r = idx >> 2, seg = idx & 3;
        uint32_t dst = base + (uint32_t)(2 * 128 * PSTR + r * PSTR + seg * 4) * 4;
        size_t so = (size_t)(col0 + r) * EMB + k0 + seg * 8;
        cp16(dst,                  g_wh + so);
        cp16(dst + 128 * PSTR * 4, g_wl + so);
    }
    CP_COMMIT();
}

__global__ void __launch_bounds__(256, 2) k_qkv(const float* __restrict__ bias)
{
    extern __shared__ uint32_t smu[];

    const int row0 = blockIdx.y * 128, col0 = blockIdx.x * 128;
    const int t = threadIdx.x, warp = t >> 5, lane = t & 31;
    const int wm = warp >> 2, wn = warp & 3;
    const int g = lane >> 2, tg = lane & 3;
    const int lr = lane & 15, lc = (lane >> 4) << 2;

    const uint32_t sbase = smaddr(smu);
    float acc[4][4][4] = {};

    qkv_issue(sbase, row0, col0, 0, t);

    for (int s = 0; s < 24; s++) {
        if (s < 23) {
            qkv_issue(sbase + ((s + 1) & 1) * (QKV_STAGE * 4), row0, col0,
                      (s + 1) * 32, t);
            asm volatile("cp.async.wait_group 1;" ::: "memory");
        } else {
            asm volatile("cp.async.wait_group 0;" ::: "memory");
        }
        __syncthreads();

        const uint32_t sb  = sbase + (s & 1) * (QKV_STAGE * 4);
        const uint32_t aAh = sb + (uint32_t)((wm * 64 + lr) * PSTR + lc) * 4;
        const uint32_t aAl = aAh + 128 * PSTR * 4;
        const uint32_t aBh = sb + (uint32_t)(2 * 128 * PSTR + (wn * 32 + lr) * PSTR + lc) * 4;
        const uint32_t aBl = aBh + 128 * PSTR * 4;

        #pragma unroll
        for (int ks = 0; ks < 2; ks++) {
            const uint32_t po = (uint32_t)(ks * 8) * 4;
            uint32_t bh[2][4], bl[2][4];
            #pragma unroll
            for (int j = 0; j < 2; j++) {
                ldsm4(bh[j], aBh + (uint32_t)(j * 16 * PSTR) * 4 + po);
                ldsm4(bl[j], aBl + (uint32_t)(j * 16 * PSTR) * 4 + po);
            }
            #pragma unroll
            for (int mi = 0; mi < 4; mi++) {
                uint32_t ah[4], al[4];
                ldsm4(ah, aAh + (uint32_t)(mi * 16 * PSTR) * 4 + po);
                ldsm4(al, aAl + (uint32_t)(mi * 16 * PSTR) * 4 + po);
                #pragma unroll
                for (int j = 0; j < 2; j++)
                    #pragma unroll
                    for (int ni = 0; ni < 2; ni++) {
                        float* c = acc[mi][j * 2 + ni];
                        mma16(c, ah, bh[j][ni], bh[j][2 + ni]);
                        mma16(c, ah, bl[j][ni], bl[j][2 + ni]);
                        mma16(c, al, bh[j][ni], bh[j][2 + ni]);
                    }
            }
        }
        __syncthreads();
    }

    const bool isV = (col0 >= 2 * EMB);
    #pragma unroll
    for (int mi = 0; mi < 4; mi++) {
        int r0 = row0 + wm * 64 + mi * 16 + g;
        #pragma unroll
        for (int q = 0; q < 4; q++) {
            int c = col0 + wn * 32 + q * 8 + 2 * tg;
            float b0 = bias[c], b1 = bias[c + 1];
            float v00 = acc[mi][q][0] + b0, v01 = acc[mi][q][1] + b1;
            float v10 = acc[mi][q][2] + b0, v11 = acc[mi][q][3] + b1;
            *reinterpret_cast<float2*>(&g_qkv[(size_t)r0       * FQKV + c]) = make_float2(v00, v01);
            *reinterpret_cast<float2*>(&g_qkv[(size_t)(r0 + 8) * FQKV + c]) = make_float2(v10, v11);
            if (isV) {
                int cv = c - 2 * EMB;
                uint32_t h0, l0, h1, l1;
                packhl(v00, v01, h0, l0);
                packhl(v10, v11, h1, l1);
                *reinterpret_cast<uint32_t*>(&g_vh[(size_t)r0       * EMB + cv]) = h0;
                *reinterpret_cast<uint32_t*>(&g_vl[(size_t)r0       * EMB + cv]) = l0;
                *reinterpret_cast<uint32_t*>(&g_vh[(size_t)(r0 + 8) * EMB + cv]) = h1;
                *reinterpret_cast<uint32_t*>(&g_vl[(size_t)(r0 + 8) * EMB + cv]) = l1;
            }
        }
    }
}

// ===========================================================================
// Output projection (unchanged)
// ===========================================================================
__global__ void __launch_bounds__(256) k_out(const float* __restrict__ w,
                                             const float* __restrict__ bias,
                                             float* __restrict__ out)
{
    extern __shared__ uint32_t smo[];
    uint32_t* Ah = smo;
    uint32_t* Bh = Ah + 128 * 36;

    const int row0 = blockIdx.y * 128, col0 = blockIdx.x * 64;
    const int t = threadIdx.x, warp = t >> 5, lane = t & 31;
    const int wm = warp >> 2, wn = warp & 3;
    const int g = lane >> 2, tg = lane & 3;
    const int lr = lane & 15, lc = (lane >> 4) << 2;

    const uint32_t aA = smaddr(Ah) + (uint32_t)((wm * 64 + lr) * 36 + lc) * 4;
    const uint32_t aB = smaddr(Bh) + (uint32_t)((wn * 16 + lr) * 36 + lc) * 4;

    float acc[4][2][4] = {};
    float4 pa[4], pb[2];

    #pragma unroll
    for (int i = 0; i < 4; i++) {
        int idx = t + i * 256;
        int r = idx >> 3, c4 = (idx & 7) * 4;
        pa[i] = *reinterpret_cast<const float4*>(&g_oh[(size_t)(row0 + r) * EMB + c4]);
    }
    #pragma unroll
    for (int i = 0; i < 2; i++) {
        int idx = t + i * 256;
        int r = idx >> 3, c4 = (idx & 7) * 4;
        pb[i] = *reinterpret_cast<const float4*>(&w[(size_t)(col0 + r) * EMB + c4]);
    }

    for (int k0 = 0; k0 < EMB; k0 += 32) {
        __syncthreads();
        #pragma unroll
        for (int i = 0; i < 4; i++) {
            int idx = t + i * 256;
            int r = idx >> 3, c4 = (idx & 7) * 4;
            Ah[r * 36 + c4 + 0] = f2tf(pa[i].x); Ah[r * 36 + c4 + 1] = f2tf(pa[i].y);
            Ah[r * 36 + c4 + 2] = f2tf(pa[i].z); Ah[r * 36 + c4 + 3] = f2tf(pa[i].w);
        }
        #pragma unroll
        for (int i = 0; i < 2; i++) {
            int idx = t + i * 256;
            int r = idx >> 3, c4 = (idx & 7) * 4;
            Bh[r * 36 + c4 + 0] = f2tf(pb[i].x); Bh[r * 36 + c4 + 1] = f2tf(pb[i].y);
            Bh[r * 36 + c4 + 2] = f2tf(pb[i].z); Bh[r * 36 + c4 + 3] = f2tf(pb[i].w);
        }
        __syncthreads();

        int kn = k0 + 32;
        if (kn < EMB) {
            #pragma unroll
            for (int i = 0; i < 4; i++) {
                int idx = t + i * 256;
                int r = idx >> 3, c4 = (idx & 7) * 4;
                pa[i] = *reinterpret_cast<const float4*>(&g_oh[(size_t)(row0 + r) * EMB + kn + c4]);
            }
            #pragma unroll
            for (int i = 0; i < 2; i++) {
                int idx = t + i * 256;
                int r = idx >> 3, c4 = (idx & 7) * 4;
                pb[i] = *reinterpret_cast<const float4*>(&w[(size_t)(col0 + r) * EMB + kn + c4]);
            }
        }

        #pragma unroll
        for (int ks = 0; ks < 4; ks++) {
            const uint32_t ko = (uint32_t)(ks * 8) * 4;
            uint32_t a[4][4], b[4];
            #pragma unroll
            for (int mi = 0; mi < 4; mi++)
                ldsm4(a[mi], aA + (uint32_t)(mi * 16 * 36) * 4 + ko);
            ldsm4(b, aB + ko);
            #pragma unroll
            for (int mi = 0; mi < 4; mi++)
                #pragma unroll
                for (int ni = 0; ni < 2; ni++)
                    mma8(acc[mi][ni], a[mi][0], a[mi][1], a[mi][2], a[mi][3],
                         b[ni], b[2 + ni]);
        }
    }

    #pragma unroll
    for (int mi = 0; mi < 4; mi++) {
        int r0 = row0 + wm * 64 + mi * 16 + g;
        #pragma unroll
        for (int ni = 0; ni < 2; ni++) {
            int c = col0 + wn * 16 + ni * 8 + 2 * tg;
            float b0 = bias[c], b1 = bias[c + 1];
            *reinterpret_cast<float2*>(&out[(size_t)r0       * EMB + c]) =
                make_float2(acc[mi][ni][0] + b0, acc[mi][ni][1] + b1);
            *reinterpret_cast<float2*>(&out[(size_t)(r0 + 8) * EMB + c]) =
                make_float2(acc[mi][ni][2] + b0, acc[mi][ni][3] + b1);
        }
    }
}

// ===========================================================================
// Fused attention v4: single-pass, S fully register-resident.
// CTA = 32 q rows, 512 threads (16 warps = 2m x 8n). K/V strips of 128 keys,
// cp.async ring-4. QK computed ONCE into Sreg[8][2][4]; softmax via register
// +shuffle+small-smem reduce; probs written once; PV split-bf16 from repack.
// ===========================================================================
#define RT2   32
#define KST2  68
#define VST2  72
#define KBUF  (128 * KST2)      // floats
#define VBUF  (128 * VST2)      // bf16 elems
#define SMO_VL   73728          // V-lo region byte offset (V-hi at 0)
#define SMO_MSC  147456         // mscr: 8*32*2*4 = 2048 B
#define SMO_FSC  (147456 + 2048)
#define SMB_ATTN (SMO_FSC + 256)   // 149760 B

__device__ __forceinline__ void a_issue_k(char* smc, const float* __restrict__ Kg,
                                          int s, int t)
{
    float* kb = (float*)smc + (size_t)(s & 3) * KBUF;
    #pragma unroll
    for (int i = 0; i < 4; i++) {
        int idx = t + i * 512;
        int r = idx >> 4, c4 = (idx & 15) * 4;
        cp16(smaddr(kb + r * KST2 + c4), Kg + (size_t)(s * 128 + r) * FQKV + c4);
    }
    CP_COMMIT();
}

__device__ __forceinline__ void a_issue_v(char* smc,
                                          const __nv_bfloat16* __restrict__ VgH,
                                          const __nv_bfloat16* __restrict__ VgL,
                                          int s, int t)
{
    __nv_bfloat16* vh = (__nv_bfloat16*)smc + (size_t)(s & 3) * VBUF;
    __nv_bfloat16* vl = (__nv_bfloat16*)(smc + SMO_VL) + (size_t)(s & 3) * VBUF;
    #pragma unroll
    for (int i = 0; i < 2; i++) {
        int idx = t + i * 512;
        int r = idx >> 3, seg = idx & 7;
        size_t go = (size_t)(s * 128 + r) * EMB + seg * 8;
        cp16(smaddr(vh + r * VST2 + seg * 8), VgH + go);
        cp16(smaddr(vl + r * VST2 + seg * 8), VgL + go);
    }
    CP_COMMIT();
}

__global__ void __launch_bounds__(512) k_attn(float* __restrict__ attn)
{
    extern __shared__ char smc[];
    float* mscr = (float*)(smc + SMO_MSC);
    float* fscr = (float*)(smc + SMO_FSC);

    const int bh = blockIdx.y;
    const int bb = bh / NHEAD, h = bh % NHEAD;
    const int row0 = blockIdx.x * RT2;
    const int t = threadIdx.x, warp = t >> 5, lane = t & 31;
    const int g = lane >> 2, tg = lane & 3;
    const int wm = warp >> 3;          // 0..1
    const int wn = warp & 7;           // 0..7
    const int lr = lane & 15, lc = (lane >> 4) << 2;

    const float* Qg = g_qkv + ((size_t)bb * SEQ + row0) * FQKV + h * HDIM;
    const float* Kg = g_qkv + (size_t)bb * SEQ * FQKV + EMB + h * HDIM;
    const __nv_bfloat16* VgH = g_vh + (size_t)bb * SEQ * EMB + h * HDIM;
    const __nv_bfloat16* VgL = g_vl + (size_t)bb * SEQ * EMB + h * HDIM;

    // ---- stage Q (32x64) in K buffer 0, pin tf32 fragments ----
    {
        float* Kb = (float*)smc;
        int r = t >> 4, c4 = (t & 15) * 4;
        float4 v = *reinterpret_cast<const float4*>(&Qg[(size_t)r * FQKV + c4]);
        Kb[r * KST2 + c4 + 0] = v.x; Kb[r * KST2 + c4 + 1] = v.y;
        Kb[r * KST2 + c4 + 2] = v.z; Kb[r * KST2 + c4 + 3] = v.w;
    }
    __syncthreads();
    uint32_t qf[8][4];
    {
        const float* Kb = (const float*)smc;
        const int rb = wm * 16;
        #pragma unroll
        for (int ks = 0; ks < 8; ks++) {
            int kb = ks * 8;
            qf[ks][0] = f2tf(Kb[(rb + g    ) * KST2 + kb + tg]);
            qf[ks][1] = f2tf(Kb[(rb + g + 8) * KST2 + kb + tg]);
            qf[ks][2] = f2tf(Kb[(rb + g    ) * KST2 + kb + tg + 4]);
            qf[ks][3] = f2tf(Kb[(rb + g + 8) * KST2 + kb + tg + 4]);
        }
    }
    __syncthreads();

    const uint32_t kfrag = (uint32_t)((wn * 16 + lr) * KST2 + lc) * 4;
    const float sc = 0.125f;

    // ---- QK^T once: 8 strips of 128 keys, ring-4 ----
    a_issue_k(smc, Kg, 0, t);
    a_issue_k(smc, Kg, 1, t);

    float Sreg[8][2][4];

    for (int s = 0; s < 8; s++) {
        if (s < 6) {
            a_issue_k(smc, Kg, s + 2, t);
            asm volatile("cp.async.wait_group 2;" ::: "memory");
        } else if (s == 6) {
            asm volatile("cp.async.wait_group 1;" ::: "memory");
        } else {
            asm volatile("cp.async.wait_group 0;" ::: "memory");
        }
        __syncthreads();
        const uint32_t kbase = smaddr((float*)smc + (size_t)(s & 3) * KBUF) + kfrag;

        float acc[2][4] = {};
        #pragma unroll
        for (int ks = 0; ks < 8; ks++) {
            uint32_t b[4];
            ldsm4(b, kbase + (uint32_t)(ks * 8) * 4);
            mma8(acc[0], qf[ks][0], qf[ks][1], qf[ks][2], qf[ks][3], b[0], b[2]);
            mma8(acc[1], qf[ks][0], qf[ks][1], qf[ks][2], qf[ks][3], b[1], b[3]);
        }
        #pragma unroll
        for (int ni = 0; ni < 2; ni++)
            #pragma unroll
            for (int v = 0; v < 4; v++)
                Sreg[s][ni][v] = acc[ni][v] * sc;
    }

    // ---- softmax stats from registers ----
    float mA = -1e30f, mB = -1e30f;
    #pragma unroll
    for (int s = 0; s < 8; s++)
        #pragma unroll
        for (int ni = 0; ni < 2; ni++) {
            mA = fmaxf(mA, fmaxf(Sreg[s][ni][0], Sreg[s][ni][1]));
            mB = fmaxf(mB, fmaxf(Sreg[s][ni][2], Sreg[s][ni][3]));
        }
    float lA = 0.0f, lB = 0.0f;
    #pragma unroll
    for (int s = 0; s < 8; s++)
        #pragma unroll
        for (int ni = 0; ni < 2; ni++) {
            lA += __expf(Sreg[s][ni][0] - mA) + __expf(Sreg[s][ni][1] - mA);
            lB += __expf(Sreg[s][ni][2] - mB) + __expf(Sreg[s][ni][3] - mB);
        }
    #pragma unroll
    for (int off = 1; off <= 2; off <<= 1) {
        float mo = __shfl_xor_sync(0xffffffffu, mA, off);
        float lo = __shfl_xor_sync(0xffffffffu, lA, off);
        float mn = fmaxf(mA, mo);
        lA = lA * __expf(mA - mn) + lo * __expf(mo - mn); mA = mn;
        mo = __shfl_xor_sync(0xffffffffu, mB, off);
        lo = __shfl_xor_sync(0xffffffffu, lB, off);
        mn = fmaxf(mB, mo);
        lB = lB * __expf(mB - mn) + lo * __expf(mo - mn); mB = mn;
    }

    // prefetch V strip 0 (K bufs it overlaps retired strips >=1 sync ago)
    a_issue_v(smc, VgH, VgL, 0, t);

    if (tg == 0) {
        mscr[(wn * 32 + wm * 16 + g    ) * 2]     = mA;
        mscr[(wn * 32 + wm * 16 + g    ) * 2 + 1] = lA;
        mscr[(wn * 32 + wm * 16 + g + 8) * 2]     = mB;
        mscr[(wn * 32 + wm * 16 + g + 8) * 2 + 1] = lB;
    }
    __syncthreads();

    a_issue_v(smc, VgH, VgL, 1, t);   // overlaps K buf3: retired, sync passed

    if (t < 32) {
        float M = -1e30f, L = 0.0f;
        #pragma unroll
        for (int j = 0; j < 8; j++) {
            float mj = mscr[(j * 32 + t) * 2];
            float lj = mscr[(j * 32 + t) * 2 + 1];
            float mn = fmaxf(M, mj);
            L = L * __expf(M - mn) + lj * __expf(mj - mn);
            M = mn;
        }
        fscr[t * 2]     = M;
        fscr[t * 2 + 1] = 1.0f / L;
    }
    __syncthreads();
    const float mf0 = fscr[(wm * 16 + g    ) * 2];
    const float iv0 = fscr[(wm * 16 + g    ) * 2 + 1];
    const float mf1 = fscr[(wm * 16 + g + 8) * 2];
    const float iv1 = fscr[(wm * 16 + g + 8) * 2 + 1];

    // ---- PV: 8 strips, V ring-4, probs written once ----
    float O[8][4] = {};
    float* ar0 = attn + ((size_t)bh * SEQ + row0 + wm * 16 + g) * SEQ;
    float* ar1 = ar0 + 8 * SEQ;

    for (int s = 0; s < 8; s++) {
        if (s < 6) {
            a_issue_v(smc, VgH, VgL, s + 2, t);
            asm volatile("cp.async.wait_group 2;" ::: "memory");
        } else if (s == 6) {
            asm volatile("cp.async.wait_group 1;" ::: "memory");
        } else {
            asm volatile("cp.async.wait_group 0;" ::: "memory");
        }
        __syncthreads();

        float p00 = __expf(Sreg[s][0][0] - mf0) * iv0;
        float p01 = __expf(Sreg[s][0][1] - mf0) * iv0;
        float p02 = __expf(Sreg[s][1][0] - mf0) * iv0;
        float p03 = __expf(Sreg[s][1][1] - mf0) * iv0;
        float q00 = __expf(Sreg[s][0][2] - mf1) * iv1;
        float q01 = __expf(Sreg[s][0][3] - mf1) * iv1;
        float q02 = __expf(Sreg[s][1][2] - mf1) * iv1;
        float q03 = __expf(Sreg[s][1][3] - mf1) * iv1;

        int c = s * 128 + wn * 16 + 2 * tg;
        *reinterpret_cast<float2*>(&ar0[c])     = make_float2(p00, p01);
        *reinterpret_cast<float2*>(&ar0[c + 8]) = make_float2(p02, p03);
        *reinterpret_cast<float2*>(&ar1[c])     = make_float2(q00, q01);
        *reinterpret_cast<float2*>(&ar1[c + 8]) = make_float2(q02, q03);

        uint32_t ah[4], al[4];
        packhl(p00, p01, ah[0], al[0]);
        packhl(q00, q01, ah[1], al[1]);
        packhl(p02, p03, ah[2], al[2]);
        packhl(q02, q03, ah[3], al[3]);

        const __nv_bfloat16* vhp = (const __nv_bfloat16*)smc +
                                   (size_t)(s & 3) * VBUF + (wn * 16 + lr) * VST2;
        const __nv_bfloat16* vlp = (const __nv_bfloat16*)(smc + SMO_VL) +
                                   (size_t)(s & 3) * VBUF + (wn * 16 + lr) * VST2;
        const uint32_t vrh = smaddr(vhp);
        const uint32_t vrl = smaddr(vlp);
        #pragma unroll
        for (int nt = 0; nt < 8; nt++) {
            uint32_t b0, b1, c0, c1;
            ldsm2t(b0, b1, vrh + (uint32_t)(nt * 8) * 2);
            ldsm2t(c0, c1, vrl + (uint32_t)(nt * 8) * 2);
            mma16(O[nt], ah, b0, b1);
            mma16(O[nt], al, b0, b1);
            mma16(O[nt], ah, c0, c1);
        }
    }

    // ---- reduce O over the 8 wn warps (reuse K/V region) ----
    __syncthreads();
    float* R = (float*)smc;
    if (wn > 0) {
        float* Rp = R + (size_t)((wn - 1) * 2 + wm) * 1024;
        #pragma unroll
        for (int nt = 0; nt < 8; nt++) {
            *reinterpret_cast<float2*>(&Rp[(g    ) * 64 + nt * 8 + 2 * tg]) =
                make_float2(O[nt][0], O[nt][1]);
            *reinterpret_cast<float2*>(&Rp[(g + 8) * 64 + nt * 8 + 2 * tg]) =
                make_float2(O[nt][2], O[nt][3]);
        }
    }
    __syncthreads();
    if (wn == 0) {
        #pragma unroll
        for (int j = 0; j < 7; j++) {
            const float* Rp = R + (size_t)(j * 2 + wm) * 1024;
            #pragma unroll
            for (int nt = 0; nt < 8; nt++) {
                float2 a0 = *reinterpret_cast<const float2*>(&Rp[(g    ) * 64 + nt * 8 + 2 * tg]);
                float2 a1 = *reinterpret_cast<const float2*>(&Rp[(g + 8) * 64 + nt * 8 + 2 * tg]);
                O[nt][0] += a0.x; O[nt][1] += a0.y;
                O[nt][2] += a1.x; O[nt][3] += a1.y;
            }
        }
        float* o0 = g_oh + ((size_t)bb * SEQ + row0 + wm * 16 + g) * EMB + h * HDIM;
        float* o1 = o0 + 8 * EMB;
        #pragma unroll
        for (int nt = 0; nt < 8; nt++) {
            *reinterpret_cast<float2*>(&o0[nt * 8 + 2 * tg]) = make_float2(O[nt][0], O[nt][1]);
            *reinterpret_cast<float2*>(&o1[nt * 8 + 2 * tg]) = make_float2(O[nt][2], O[nt][3]);
        }
    }
}

// ---------------------------------------------------------------------------
extern "C" void kernel_launch(void* const* d_in, const int* in_sizes, int n_in,
                              void* d_out, int out_size)
{
    const float* x     = (const float*)d_in[0];
    const float* w_qkv = (const float*)d_in[1];
    const float* b_qkv = (const float*)d_in[2];
    const float* w_out = (const float*)d_in[3];
    const float* b_out = (const float*)d_in[4];

    float* out  = (float*)d_out;
    float* attn = out + (size_t)MTOT * EMB;

    const int smem_qkv  = 2 * QKV_STAGE * 4;          // 81920
    const int smem_out  = (128 * 36 + 64 * 36) * 4;   // 27648
    const int smem_attn = SMB_ATTN;                   // 149760

    static bool attr_done = false;
    if (!attr_done) {
        cudaFuncSetAttribute(k_qkv,  cudaFuncAttributeMaxDynamicSharedMemorySize, smem_qkv);
        cudaFuncSetAttribute(k_out,  cudaFuncAttributeMaxDynamicSharedMemorySize, smem_out);
        cudaFuncSetAttribute(k_attn, cudaFuncAttributeMaxDynamicSharedMemorySize, smem_attn);
        attr_done = true;
    }

    __nv_bfloat16 *xh, *xl, *wh, *wl;
    cudaGetSymbolAddress((void**)&xh, g_xh);
    cudaGetSymbolAddress((void**)&xl, g_xl);
    cudaGetSymbolAddress((void**)&wh, g_wh);
    cudaGetSymbolAddress((void**)&wl, g_wl);

    const int nx4 = MTOT * EMB / 4;
    const int nw4 = FQKV * EMB / 4;

    k_split<<<(nx4 + 255) / 256, 256>>>(x,     xh, xl, nx4);
    k_split<<<(nw4 + 255) / 256, 256>>>(w_qkv, wh, wl, nw4);

    k_qkv <<<dim3(FQKV / 128, MTOT / 128), 256, smem_qkv >>>(b_qkv);
    k_attn<<<dim3(SEQ / RT2, BHTOT),       512, smem_attn>>>(attn);
    k_out <<<dim3(EMB / 64, MTOT / 128),   256, smem_out >>>(w_out, b_out, out);
}

// round 13
// speedup vs baseline: 1.1288x; 1.0123x over previous
#include <cuda_runtime.h>
#include <cuda_bf16.h>
#include <math.h>
#include <stdint.h>

#define EMB   768
#define NHEAD 12
#define HDIM  64
#define SEQ   1024
#define BATCH 8
#define MTOT  (BATCH * SEQ)
#define FQKV  (3 * EMB)
#define BHTOT (BATCH * NHEAD)

__device__ float g_qkv[(size_t)MTOT * FQKV];
__device__ float g_oh [(size_t)MTOT * EMB];
__device__ __nv_bfloat16 g_vh[(size_t)MTOT * EMB];
__device__ __nv_bfloat16 g_vl[(size_t)MTOT * EMB];
__device__ __nv_bfloat16 g_xh[(size_t)MTOT * EMB];
__device__ __nv_bfloat16 g_xl[(size_t)MTOT * EMB];
__device__ __nv_bfloat16 g_wh[(size_t)FQKV * EMB];
__device__ __nv_bfloat16 g_wl[(size_t)FQKV * EMB];

__device__ __forceinline__ uint32_t f2tf(float x) {
    uint32_t r;
    asm("cvt.rna.tf32.f32 %0, %1;" : "=r"(r) : "f"(x));
    return r;
}
__device__ __forceinline__ float ex2f(float x) {
    float r;
    asm("ex2.approx.f32 %0, %1;" : "=f"(r) : "f"(x));
    return r;
}
__device__ __forceinline__ uint32_t smaddr(const void* p) {
    return (uint32_t)__cvta_generic_to_shared(p);
}
__device__ __forceinline__ void ldsm4(uint32_t* r, uint32_t a) {
    asm volatile("ldmatrix.sync.aligned.m8n8.x4.shared.b16 {%0,%1,%2,%3}, [%4];"
                 : "=r"(r[0]), "=r"(r[1]), "=r"(r[2]), "=r"(r[3]) : "r"(a));
}
__device__ __forceinline__ void ldsm2t(uint32_t& r0, uint32_t& r1, uint32_t a) {
    asm volatile("ldmatrix.sync.aligned.m8n8.x2.trans.shared.b16 {%0,%1}, [%2];"
                 : "=r"(r0), "=r"(r1) : "r"(a));
}
__device__ __forceinline__ void cp16(uint32_t dst, const void* src) {
    asm volatile("cp.async.cg.shared.global [%0], [%1], 16;" :: "r"(dst), "l"(src));
}
#define CP_COMMIT() asm volatile("cp.async.commit_group;" ::: "memory")

__device__ __forceinline__ void mma8(float* c,
                                     uint32_t a0, uint32_t a1, uint32_t a2, uint32_t a3,
                                     uint32_t b0, uint32_t b1)
{
    asm volatile(
        "mma.sync.aligned.m16n8k8.row.col.f32.tf32.tf32.f32 "
        "{%0,%1,%2,%3}, {%4,%5,%6,%7}, {%8,%9}, {%0,%1,%2,%3};\n"
        : "+f"(c[0]), "+f"(c[1]), "+f"(c[2]), "+f"(c[3])
        : "r"(a0), "r"(a1), "r"(a2), "r"(a3), "r"(b0), "r"(b1));
}
__device__ __forceinline__ void mma16(float* c, const uint32_t* a,
                                      uint32_t b0, uint32_t b1)
{
    asm volatile(
        "mma.sync.aligned.m16n8k16.row.col.f32.bf16.bf16.f32 "
        "{%0,%1,%2,%3}, {%4,%5,%6,%7}, {%8,%9}, {%0,%1,%2,%3};\n"
        : "+f"(c[0]), "+f"(c[1]), "+f"(c[2]), "+f"(c[3])
        : "r"(a[0]), "r"(a[1]), "r"(a[2]), "r"(a[3]), "r"(b0), "r"(b1));
}

__device__ __forceinline__ void packhl(float x, float y, uint32_t& hi, uint32_t& lo)
{
    __nv_bfloat162 h = __floats2bfloat162_rn(x, y);
    hi = *reinterpret_cast<uint32_t*>(&h);
    __nv_bfloat162 l = __floats2bfloat162_rn(x - __bfloat162float(h.x),
                                             y - __bfloat162float(h.y));
    lo = *reinterpret_cast<uint32_t*>(&l);
}

// ===========================================================================
// Pre-split x / w_qkv to bf16 hi/lo
// ===========================================================================
__global__ void __launch_bounds__(256) k_split(const float* __restrict__ src,
                                               __nv_bfloat16* __restrict__ hi,
                                               __nv_bfloat16* __restrict__ lo,
                                               int n4)
{
    int i = blockIdx.x * blockDim.x + threadIdx.x;
    if (i >= n4) return;
    float4 v = reinterpret_cast<const float4*>(src)[i];
    uint32_t h0, l0, h1, l1;
    packhl(v.x, v.y, h0, l0);
    packhl(v.z, v.w, h1, l1);
    reinterpret_cast<uint32_t*>(hi)[i * 2]     = h0;
    reinterpret_cast<uint32_t*>(hi)[i * 2 + 1] = h1;
    reinterpret_cast<uint32_t*>(lo)[i * 2]     = l0;
    reinterpret_cast<uint32_t*>(lo)[i * 2 + 1] = l1;
}

// ===========================================================================
// QKV projection (R11 version, unchanged): 128x128 block, split bf16,
// cp.async double-buffered, bf16 hi/lo V side-copy in epilogue.
// ===========================================================================
#define PSTR 20
#define QKV_STAGE (4 * 128 * PSTR)

__device__ __forceinline__ void qkv_issue(uint32_t base, int row0, int col0,
                                          int k0, int t)
{
    #pragma unroll
    for (int i = 0; i < 2; i++) {
        int idx = t + i * 256;
        int r = idx >> 2, seg = idx & 3;
        uint32_t dst = base + (uint32_t)(r * PSTR + seg * 4) * 4;
        size_t so = (size_t)(row0 + r) * EMB + k0 + seg * 8;
        cp16(dst,                  g_xh + so);
        cp16(dst + 128 * PSTR * 4, g_xl + so);
    }
    #pragma unroll
    for (int i = 0; i < 2; i++) {
        int idx = t + i * 256;
        int r = idx >> 2, seg = idx & 3;
        uint32_t dst = base + (uint32_t)(2 * 128 * PSTR + r * PSTR + seg * 4) * 4;
        size_t so = (size_t)(col0 + r) * EMB + k0 + seg * 8;
        cp16(dst,                  g_wh + so);
        cp16(dst + 128 * PSTR * 4, g_wl + so);
    }
    CP_COMMIT();
}

__global__ void __launch_bounds__(256, 2) k_qkv(const float* __restrict__ bias)
{
    extern __shared__ uint32_t smu[];

    const int row0 = blockIdx.y * 128, col0 = blockIdx.x * 128;
    const int t = threadIdx.x, warp = t >> 5, lane = t & 31;
    const int wm = warp >> 2, wn = warp & 3;
    const int g = lane >> 2, tg = lane & 3;
    const int lr = lane & 15, lc = (lane >> 4) << 2;

    const uint32_t sbase = smaddr(smu);
    float acc[4][4][4] = {};

    qkv_issue(sbase, row0, col0, 0, t);

    for (int s = 0; s < 24; s++) {
        if (s < 23) {
            qkv_issue(sbase + ((s + 1) & 1) * (QKV_STAGE * 4), row0, col0,
                      (s + 1) * 32, t);
            asm volatile("cp.async.wait_group 1;" ::: "memory");
        } else {
            asm volatile("cp.async.wait_group 0;" ::: "memory");
        }
        __syncthreads();

        const uint32_t sb  = sbase + (s & 1) * (QKV_STAGE * 4);
        const uint32_t aAh = sb + (uint32_t)((wm * 64 + lr) * PSTR + lc) * 4;
        const uint32_t aAl = aAh + 128 * PSTR * 4;
        const uint32_t aBh = sb + (uint32_t)(2 * 128 * PSTR + (wn * 32 + lr) * PSTR + lc) * 4;
        const uint32_t aBl = aBh + 128 * PSTR * 4;

        #pragma unroll
        for (int ks = 0; ks < 2; ks++) {
            const uint32_t po = (uint32_t)(ks * 8) * 4;
            uint32_t bh[2][4], bl[2][4];
            #pragma unroll
            for (int j = 0; j < 2; j++) {
                ldsm4(bh[j], aBh + (uint32_t)(j * 16 * PSTR) * 4 + po);
                ldsm4(bl[j], aBl + (uint32_t)(j * 16 * PSTR) * 4 + po);
            }
            #pragma unroll
            for (int mi = 0; mi < 4; mi++) {
                uint32_t ah[4], al[4];
                ldsm4(ah, aAh + (uint32_t)(mi * 16 * PSTR) * 4 + po);
                ldsm4(al, aAl + (uint32_t)(mi * 16 * PSTR) * 4 + po);
                #pragma unroll
                for (int j = 0; j < 2; j++)
                    #pragma unroll
                    for (int ni = 0; ni < 2; ni++) {
                        float* c = acc[mi][j * 2 + ni];
                        mma16(c, ah, bh[j][ni], bh[j][2 + ni]);
                        mma16(c, ah, bl[j][ni], bl[j][2 + ni]);
                        mma16(c, al, bh[j][ni], bh[j][2 + ni]);
                    }
            }
        }
        __syncthreads();
    }

    const bool isV = (col0 >= 2 * EMB);
    #pragma unroll
    for (int mi = 0; mi < 4; mi++) {
        int r0 = row0 + wm * 64 + mi * 16 + g;
        #pragma unroll
        for (int q = 0; q < 4; q++) {
            int c = col0 + wn * 32 + q * 8 + 2 * tg;
            float b0 = bias[c], b1 = bias[c + 1];
            float v00 = acc[mi][q][0] + b0, v01 = acc[mi][q][1] + b1;
            float v10 = acc[mi][q][2] + b0, v11 = acc[mi][q][3] + b1;
            *reinterpret_cast<float2*>(&g_qkv[(size_t)r0       * FQKV + c]) = make_float2(v00, v01);
            *reinterpret_cast<float2*>(&g_qkv[(size_t)(r0 + 8) * FQKV + c]) = make_float2(v10, v11);
            if (isV) {
                int cv = c - 2 * EMB;
                uint32_t h0, l0, h1, l1;
                packhl(v00, v01, h0, l0);
                packhl(v10, v11, h1, l1);
                *reinterpret_cast<uint32_t*>(&g_vh[(size_t)r0       * EMB + cv]) = h0;
                *reinterpret_cast<uint32_t*>(&g_vl[(size_t)r0       * EMB + cv]) = l0;
                *reinterpret_cast<uint32_t*>(&g_vh[(size_t)(r0 + 8) * EMB + cv]) = h1;
                *reinterpret_cast<uint32_t*>(&g_vl[(size_t)(r0 + 8) * EMB + cv]) = l1;
            }
        }
    }
}

// ===========================================================================
// Output projection: tf32, 128x128 tile (8 warps, warp 64x32), reg prefetch.
// ===========================================================================
__global__ void __launch_bounds__(256) k_out(const float* __restrict__ w,
                                             const float* __restrict__ bias,
                                             float* __restrict__ out)
{
    extern __shared__ uint32_t smo[];
    uint32_t* Ah = smo;             // 128*36
    uint32_t* Bh = Ah + 128 * 36;   // 128*36

    const int row0 = blockIdx.y * 128, col0 = blockIdx.x * 128;
    const int t = threadIdx.x, warp = t >> 5, lane = t & 31;
    const int wm = warp >> 2, wn = warp & 3;
    const int g = lane >> 2, tg = lane & 3;
    const int lr = lane & 15, lc = (lane >> 4) << 2;

    const uint32_t aA = smaddr(Ah) + (uint32_t)((wm * 64 + lr) * 36 + lc) * 4;
    const uint32_t aB = smaddr(Bh) + (uint32_t)((wn * 32 + lr) * 36 + lc) * 4;

    float acc[4][4][4] = {};
    float4 pa[4], pb[4];

    #pragma unroll
    for (int i = 0; i < 4; i++) {
        int idx = t + i * 256;
        int r = idx >> 3, c4 = (idx & 7) * 4;
        pa[i] = *reinterpret_cast<const float4*>(&g_oh[(size_t)(row0 + r) * EMB + c4]);
        pb[i] = *reinterpret_cast<const float4*>(&w[(size_t)(col0 + r) * EMB + c4]);
    }

    for (int k0 = 0; k0 < EMB; k0 += 32) {
        __syncthreads();
        #pragma unroll
        for (int i = 0; i < 4; i++) {
            int idx = t + i * 256;
            int r = idx >> 3, c4 = (idx & 7) * 4;
            Ah[r * 36 + c4 + 0] = f2tf(pa[i].x); Ah[r * 36 + c4 + 1] = f2tf(pa[i].y);
            Ah[r * 36 + c4 + 2] = f2tf(pa[i].z); Ah[r * 36 + c4 + 3] = f2tf(pa[i].w);
            Bh[r * 36 + c4 + 0] = f2tf(pb[i].x); Bh[r * 36 + c4 + 1] = f2tf(pb[i].y);
            Bh[r * 36 + c4 + 2] = f2tf(pb[i].z); Bh[r * 36 + c4 + 3] = f2tf(pb[i].w);
        }
        __syncthreads();

        int kn = k0 + 32;
        if (kn < EMB) {
            #pragma unroll
            for (int i = 0; i < 4; i++) {
                int idx = t + i * 256;
                int r = idx >> 3, c4 = (idx & 7) * 4;
                pa[i] = *reinterpret_cast<const float4*>(&g_oh[(size_t)(row0 + r) * EMB + kn + c4]);
                pb[i] = *reinterpret_cast<const float4*>(&w[(size_t)(col0 + r) * EMB + kn + c4]);
            }
        }

        #pragma unroll
        for (int ks = 0; ks < 4; ks++) {
            const uint32_t ko = (uint32_t)(ks * 8) * 4;
            uint32_t a[4][4], b[2][4];
            ldsm4(b[0], aB + ko);
            ldsm4(b[1], aB + (uint32_t)(16 * 36) * 4 + ko);
            #pragma unroll
            for (int mi = 0; mi < 4; mi++)
                ldsm4(a[mi], aA + (uint32_t)(mi * 16 * 36) * 4 + ko);
            #pragma unroll
            for (int mi = 0; mi < 4; mi++)
                #pragma unroll
                for (int j = 0; j < 2; j++)
                    #pragma unroll
                    for (int ni = 0; ni < 2; ni++)
                        mma8(acc[mi][j * 2 + ni], a[mi][0], a[mi][1], a[mi][2], a[mi][3],
                             b[j][ni], b[j][2 + ni]);
        }
    }

    #pragma unroll
    for (int mi = 0; mi < 4; mi++) {
        int r0 = row0 + wm * 64 + mi * 16 + g;
        #pragma unroll
        for (int q = 0; q < 4; q++) {
            int c = col0 + wn * 32 + q * 8 + 2 * tg;
            float b0 = bias[c], b1 = bias[c + 1];
            *reinterpret_cast<float2*>(&out[(size_t)r0       * EMB + c]) =
                make_float2(acc[mi][q][0] + b0, acc[mi][q][1] + b1);
            *reinterpret_cast<float2*>(&out[(size_t)(r0 + 8) * EMB + c]) =
                make_float2(acc[mi][q][2] + b0, acc[mi][q][3] + b1);
        }
    }
}

// ===========================================================================
// Fused attention v4 (R11) with softmax in log2 domain (ex2, folded scale).
// ===========================================================================
#define RT2   32
#define KST2  68
#define VST2  72
#define KBUF  (128 * KST2)
#define VBUF  (128 * VST2)
#define SMO_VL   73728
#define SMO_MSC  147456
#define SMO_FSC  (147456 + 2048)
#define SMB_ATTN (SMO_FSC + 256)

__device__ __forceinline__ void a_issue_k(char* smc, const float* __restrict__ Kg,
                                          int s, int t)
{
    float* kb = (float*)smc + (size_t)(s & 3) * KBUF;
    #pragma unroll
    for (int i = 0; i < 4; i++) {
        int idx = t + i * 512;
        int r = idx >> 4, c4 = (idx & 15) * 4;
        cp16(smaddr(kb + r * KST2 + c4), Kg + (size_t)(s * 128 + r) * FQKV + c4);
    }
    CP_COMMIT();
}

__device__ __forceinline__ void a_issue_v(char* smc,
                                          const __nv_bfloat16* __restrict__ VgH,
                                          const __nv_bfloat16* __restrict__ VgL,
                                          int s, int t)
{
    __nv_bfloat16* vh = (__nv_bfloat16*)smc + (size_t)(s & 3) * VBUF;
    __nv_bfloat16* vl = (__nv_bfloat16*)(smc + SMO_VL) + (size_t)(s & 3) * VBUF;
    #pragma unroll
    for (int i = 0; i < 2; i++) {
        int idx = t + i * 512;
        int r = idx >> 3, seg = idx & 7;
        size_t go = (size_t)(s * 128 + r) * EMB + seg * 8;
        cp16(smaddr(vh + r * VST2 + seg * 8), VgH + go);
        cp16(smaddr(vl + r * VST2 + seg * 8), VgL + go);
    }
    CP_COMMIT();
}

__global__ void __launch_bounds__(512) k_attn(float* __restrict__ attn)
{
    extern __shared__ char smc[];
    float* mscr = (float*)(smc + SMO_MSC);
    float* fscr = (float*)(smc + SMO_FSC);

    const int bh = blockIdx.y;
    const int bb = bh / NHEAD, h = bh % NHEAD;
    const int row0 = blockIdx.x * RT2;
    const int t = threadIdx.x, warp = t >> 5, lane = t & 31;
    const int g = lane >> 2, tg = lane & 3;
    const int wm = warp >> 3;
    const int wn = warp & 7;
    const int lr = lane & 15, lc = (lane >> 4) << 2;

    const float* Qg = g_qkv + ((size_t)bb * SEQ + row0) * FQKV + h * HDIM;
    const float* Kg = g_qkv + (size_t)bb * SEQ * FQKV + EMB + h * HDIM;
    const __nv_bfloat16* VgH = g_vh + (size_t)bb * SEQ * EMB + h * HDIM;
    const __nv_bfloat16* VgL = g_vl + (size_t)bb * SEQ * EMB + h * HDIM;

    {
        float* Kb = (float*)smc;
        int r = t >> 4, c4 = (t & 15) * 4;
        float4 v = *reinterpret_cast<const float4*>(&Qg[(size_t)r * FQKV + c4]);
        Kb[r * KST2 + c4 + 0] = v.x; Kb[r * KST2 + c4 + 1] = v.y;
        Kb[r * KST2 + c4 + 2] = v.z; Kb[r * KST2 + c4 + 3] = v.w;
    }
    __syncthreads();
    uint32_t qf[8][4];
    {
        const float* Kb = (const float*)smc;
        const int rb = wm * 16;
        #pragma unroll
        for (int ks = 0; ks < 8; ks++) {
            int kb = ks * 8;
            qf[ks][0] = f2tf(Kb[(rb + g    ) * KST2 + kb + tg]);
            qf[ks][1] = f2tf(Kb[(rb + g + 8) * KST2 + kb + tg]);
            qf[ks][2] = f2tf(Kb[(rb + g    ) * KST2 + kb + tg + 4]);
            qf[ks][3] = f2tf(Kb[(rb + g + 8) * KST2 + kb + tg + 4]);
        }
    }
    __syncthreads();

    const uint32_t kfrag = (uint32_t)((wn * 16 + lr) * KST2 + lc) * 4;
    // scores scaled into log2 domain: s_log2 = (q.k) * 0.125 * log2(e)
    const float sc2 = 0.125f * 1.4426950408889634f;

    a_issue_k(smc, Kg, 0, t);
    a_issue_k(smc, Kg, 1, t);

    float Sreg[8][2][4];

    for (int s = 0; s < 8; s++) {
        if (s < 6) {
            a_issue_k(smc, Kg, s + 2, t);
            asm volatile("cp.async.wait_group 2;" ::: "memory");
        } else if (s == 6) {
            asm volatile("cp.async.wait_group 1;" ::: "memory");
        } else {
            asm volatile("cp.async.wait_group 0;" ::: "memory");
        }
        __syncthreads();
        const uint32_t kbase = smaddr((float*)smc + (size_t)(s & 3) * KBUF) + kfrag;

        float acc[2][4] = {};
        #pragma unroll
        for (int ks = 0; ks < 8; ks++) {
            uint32_t b[4];
            ldsm4(b, kbase + (uint32_t)(ks * 8) * 4);
            mma8(acc[0], qf[ks][0], qf[ks][1], qf[ks][2], qf[ks][3], b[0], b[2]);
            mma8(acc[1], qf[ks][0], qf[ks][1], qf[ks][2], qf[ks][3], b[1], b[3]);
        }
        #pragma unroll
        for (int ni = 0; ni < 2; ni++)
            #pragma unroll
            for (int v = 0; v < 4; v++)
                Sreg[s][ni][v] = acc[ni][v] * sc2;
    }

    // ---- softmax stats in log2 domain ----
    float mA = -1e30f, mB = -1e30f;
    #pragma unroll
    for (int s = 0; s < 8; s++)
        #pragma unroll
        for (int ni = 0; ni < 2; ni++) {
            mA = fmaxf(mA, fmaxf(Sreg[s][ni][0], Sreg[s][ni][1]));
            mB = fmaxf(mB, fmaxf(Sreg[s][ni][2], Sreg[s][ni][3]));
        }
    float lA = 0.0f, lB = 0.0f;
    #pragma unroll
    for (int s = 0; s < 8; s++)
        #pragma unroll
        for (int ni = 0; ni < 2; ni++) {
            lA += ex2f(Sreg[s][ni][0] - mA) + ex2f(Sreg[s][ni][1] - mA);
            lB += ex2f(Sreg[s][ni][2] - mB) + ex2f(Sreg[s][ni][3] - mB);
        }
    #pragma unroll
    for (int off = 1; off <= 2; off <<= 1) {
        float mo = __shfl_xor_sync(0xffffffffu, mA, off);
        float lo = __shfl_xor_sync(0xffffffffu, lA, off);
        float mn = fmaxf(mA, mo);
        lA = lA * ex2f(mA - mn) + lo * ex2f(mo - mn); mA = mn;
        mo = __shfl_xor_sync(0xffffffffu, mB, off);
        lo = __shfl_xor_sync(0xffffffffu, lB, off);
        mn = fmaxf(mB, mo);
        lB = lB * ex2f(mB - mn) + lo * ex2f(mo - mn); mB = mn;
    }

    a_issue_v(smc, VgH, VgL, 0, t);

    if (tg == 0) {
        mscr[(wn * 32 + wm * 16 + g    ) * 2]     = mA;
        mscr[(wn * 32 + wm * 16 + g    ) * 2 + 1] = lA;
        mscr[(wn * 32 + wm * 16 + g + 8) * 2]     = mB;
        mscr[(wn * 32 + wm * 16 + g + 8) * 2 + 1] = lB;
    }
    __syncthreads();

    a_issue_v(smc, VgH, VgL, 1, t);

    if (t < 32) {
        float M = -1e30f, L = 0.0f;
        #pragma unroll
        for (int j = 0; j < 8; j++) {
            float mj = mscr[(j * 32 + t) * 2];
            float lj = mscr[(j * 32 + t) * 2 + 1];
            float mn = fmaxf(M, mj);
            L = L * ex2f(M - mn) + lj * ex2f(mj - mn);
            M = mn;
        }
        fscr[t * 2]     = M;
        fscr[t * 2 + 1] = 1.0f / L;
    }
    __syncthreads();
    const float mf0 = fscr[(wm * 16 + g    ) * 2];
    const float iv0 = fscr[(wm * 16 + g    ) * 2 + 1];
    const float mf1 = fscr[(wm * 16 + g + 8) * 2];
    const float iv1 = fscr[(wm * 16 + g + 8) * 2 + 1];

    float O[8][4] = {};
    float* ar0 = attn + ((size_t)bh * SEQ + row0 + wm * 16 + g) * SEQ;
    float* ar1 = ar0 + 8 * SEQ;

    for (int s = 0; s < 8; s++) {
        if (s < 6) {
            a_issue_v(smc, VgH, VgL, s + 2, t);
            asm volatile("cp.async.wait_group 2;" ::: "memory");
        } else if (s == 6) {
            asm volatile("cp.async.wait_group 1;" ::: "memory");
        } else {
            asm volatile("cp.async.wait_group 0;" ::: "memory");
        }
        __syncthreads();

        float p00 = ex2f(Sreg[s][0][0] - mf0) * iv0;
        float p01 = ex2f(Sreg[s][0][1] - mf0) * iv0;
        float p02 = ex2f(Sreg[s][1][0] - mf0) * iv0;
        float p03 = ex2f(Sreg[s][1][1] - mf0) * iv0;
        float q00 = ex2f(Sreg[s][0][2] - mf1) * iv1;
        float q01 = ex2f(Sreg[s][0][3] - mf1) * iv1;
        float q02 = ex2f(Sreg[s][1][2] - mf1) * iv1;
        float q03 = ex2f(Sreg[s][1][3] - mf1) * iv1;

        int c = s * 128 + wn * 16 + 2 * tg;
        *reinterpret_cast<float2*>(&ar0[c])     = make_float2(p00, p01);
        *reinterpret_cast<float2*>(&ar0[c + 8]) = make_float2(p02, p03);
        *reinterpret_cast<float2*>(&ar1[c])     = make_float2(q00, q01);
        *reinterpret_cast<float2*>(&ar1[c + 8]) = make_float2(q02, q03);

        uint32_t ah[4], al[4];
        packhl(p00, p01, ah[0], al[0]);
        packhl(q00, q01, ah[1], al[1]);
        packhl(p02, p03, ah[2], al[2]);
        packhl(q02, q03, ah[3], al[3]);

        const __nv_bfloat16* vhp = (const __nv_bfloat16*)smc +
                                   (size_t)(s & 3) * VBUF + (wn * 16 + lr) * VST2;
        const __nv_bfloat16* vlp = (const __nv_bfloat16*)(smc + SMO_VL) +
                                   (size_t)(s & 3) * VBUF + (wn * 16 + lr) * VST2;
        const uint32_t vrh = smaddr(vhp);
        const uint32_t vrl = smaddr(vlp);
        #pragma unroll
        for (int nt = 0; nt < 8; nt++) {
            uint32_t b0, b1, c0, c1;
            ldsm2t(b0, b1, vrh + (uint32_t)(nt * 8) * 2);
            ldsm2t(c0, c1, vrl + (uint32_t)(nt * 8) * 2);
            mma16(O[nt], ah, b0, b1);
            mma16(O[nt], al, b0, b1);
            mma16(O[nt], ah, c0, c1);
        }
    }

    __syncthreads();
    float* R = (float*)smc;
    if (wn > 0) {
        float* Rp = R + (size_t)((wn - 1) * 2 + wm) * 1024;
        #pragma unroll
        for (int nt = 0; nt < 8; nt++) {
            *reinterpret_cast<float2*>(&Rp[(g    ) * 64 + nt * 8 + 2 * tg]) =
                make_float2(O[nt][0], O[nt][1]);
            *reinterpret_cast<float2*>(&Rp[(g + 8) * 64 + nt * 8 + 2 * tg]) =
                make_float2(O[nt][2], O[nt][3]);
        }
    }
    __syncthreads();
    if (wn == 0) {
        #pragma unroll
        for (int j = 0; j < 7; j++) {
            const float* Rp = R + (size_t)(j * 2 + wm) * 1024;
            #pragma unroll
            for (int nt = 0; nt < 8; nt++) {
                float2 a0 = *reinterpret_cast<const float2*>(&Rp[(g    ) * 64 + nt * 8 + 2 * tg]);
                float2 a1 = *reinterpret_cast<const float2*>(&Rp[(g + 8) * 64 + nt * 8 + 2 * tg]);
                O[nt][0] += a0.x; O[nt][1] += a0.y;
                O[nt][2] += a1.x; O[nt][3] += a1.y;
            }
        }
        float* o0 = g_oh + ((size_t)bb * SEQ + row0 + wm * 16 + g) * EMB + h * HDIM;
        float* o1 = o0 + 8 * EMB;
        #pragma unroll
        for (int nt = 0; nt < 8; nt++) {
            *reinterpret_cast<float2*>(&o0[nt * 8 + 2 * tg]) = make_float2(O[nt][0], O[nt][1]);
            *reinterpret_cast<float2*>(&o1[nt * 8 + 2 * tg]) = make_float2(O[nt][2], O[nt][3]);
        }
    }
}

// ---------------------------------------------------------------------------
extern "C" void kernel_launch(void* const* d_in, const int* in_sizes, int n_in,
                              void* d_out, int out_size)
{
    const float* x     = (const float*)d_in[0];
    const float* w_qkv = (const float*)d_in[1];
    const float* b_qkv = (const float*)d_in[2];
    const float* w_out = (const float*)d_in[3];
    const float* b_out = (const float*)d_in[4];

    float* out  = (float*)d_out;
    float* attn = out + (size_t)MTOT * EMB;

    const int smem_qkv  = 2 * QKV_STAGE * 4;          // 81920
    const int smem_out  = (128 * 36 + 128 * 36) * 4;  // 36864
    const int smem_attn = SMB_ATTN;                   // 149760

    static bool attr_done = false;
    if (!attr_done) {
        cudaFuncSetAttribute(k_qkv,  cudaFuncAttributeMaxDynamicSharedMemorySize, smem_qkv);
        cudaFuncSetAttribute(k_out,  cudaFuncAttributeMaxDynamicSharedMemorySize, smem_out);
        cudaFuncSetAttribute(k_attn, cudaFuncAttributeMaxDynamicSharedMemorySize, smem_attn);
        attr_done = true;
    }

    __nv_bfloat16 *xh, *xl, *wh, *wl;
    cudaGetSymbolAddress((void**)&xh, g_xh);
    cudaGetSymbolAddress((void**)&xl, g_xl);
    cudaGetSymbolAddress((void**)&wh, g_wh);
    cudaGetSymbolAddress((void**)&wl, g_wl);

    const int nx4 = MTOT * EMB / 4;
    const int nw4 = FQKV * EMB / 4;

    k_split<<<(nx4 + 255) / 256, 256>>>(x,     xh, xl, nx4);
    k_split<<<(nw4 + 255) / 256, 256>>>(w_qkv, wh, wl, nw4);

    k_qkv <<<dim3(FQKV / 128, MTOT / 128), 256, smem_qkv >>>(b_qkv);
    k_attn<<<dim3(SEQ / RT2, BHTOT),       512, smem_attn>>>(attn);
    k_out <<<dim3(EMB / 128, MTOT / 128),  256, smem_out >>>(w_out, b_out, out);
}

// round 17
// speedup vs baseline: 1.2021x; 1.0650x over previous
#include <cuda_runtime.h>
#include <cuda_bf16.h>
#include <math.h>
#include <stdint.h>

#define EMB   768
#define NHEAD 12
#define HDIM  64
#define SEQ   1024
#define BATCH 8
#define MTOT  (BATCH * SEQ)
#define FQKV  (3 * EMB)
#define BHTOT (BATCH * NHEAD)

__device__ float g_qkv[(size_t)MTOT * FQKV];
__device__ float g_oh [(size_t)MTOT * EMB];
__device__ __nv_bfloat16 g_vh[(size_t)MTOT * EMB];
__device__ __nv_bfloat16 g_xh[(size_t)MTOT * EMB];
__device__ __nv_bfloat16 g_xl[(size_t)MTOT * EMB];
__device__ __nv_bfloat16 g_wh[(size_t)FQKV * EMB];
__device__ __nv_bfloat16 g_wl[(size_t)FQKV * EMB];

__device__ __forceinline__ uint32_t f2tf(float x) {
    uint32_t r;
    asm("cvt.rna.tf32.f32 %0, %1;" : "=r"(r) : "f"(x));
    return r;
}
__device__ __forceinline__ float ex2f(float x) {
    float r;
    asm("ex2.approx.f32 %0, %1;" : "=f"(r) : "f"(x));
    return r;
}
__device__ __forceinline__ uint32_t smaddr(const void* p) {
    return (uint32_t)__cvta_generic_to_shared(p);
}
__device__ __forceinline__ void ldsm4(uint32_t* r, uint32_t a) {
    asm volatile("ldmatrix.sync.aligned.m8n8.x4.shared.b16 {%0,%1,%2,%3}, [%4];"
                 : "=r"(r[0]), "=r"(r[1]), "=r"(r[2]), "=r"(r[3]) : "r"(a));
}
__device__ __forceinline__ void ldsm4t(uint32_t* r, uint32_t a) {
    asm volatile("ldmatrix.sync.aligned.m8n8.x4.trans.shared.b16 {%0,%1,%2,%3}, [%4];"
                 : "=r"(r[0]), "=r"(r[1]), "=r"(r[2]), "=r"(r[3]) : "r"(a));
}
__device__ __forceinline__ void cp16(uint32_t dst, const void* src) {
    asm volatile("cp.async.cg.shared.global [%0], [%1], 16;" :: "r"(dst), "l"(src));
}
#define CP_COMMIT() asm volatile("cp.async.commit_group;" ::: "memory")

__device__ __forceinline__ void mma8(float* c,
                                     uint32_t a0, uint32_t a1, uint32_t a2, uint32_t a3,
                                     uint32_t b0, uint32_t b1)
{
    asm volatile(
        "mma.sync.aligned.m16n8k8.row.col.f32.tf32.tf32.f32 "
        "{%0,%1,%2,%3}, {%4,%5,%6,%7}, {%8,%9}, {%0,%1,%2,%3};\n"
        : "+f"(c[0]), "+f"(c[1]), "+f"(c[2]), "+f"(c[3])
        : "r"(a0), "r"(a1), "r"(a2), "r"(a3), "r"(b0), "r"(b1));
}
__device__ __forceinline__ void mma16(float* c, const uint32_t* a,
                                      uint32_t b0, uint32_t b1)
{
    asm volatile(
        "mma.sync.aligned.m16n8k16.row.col.f32.bf16.bf16.f32 "
        "{%0,%1,%2,%3}, {%4,%5,%6,%7}, {%8,%9}, {%0,%1,%2,%3};\n"
        : "+f"(c[0]), "+f"(c[1]), "+f"(c[2]), "+f"(c[3])
        : "r"(a[0]), "r"(a[1]), "r"(a[2]), "r"(a[3]), "r"(b0), "r"(b1));
}

__device__ __forceinline__ void packhl(float x, float y, uint32_t& hi, uint32_t& lo)
{
    __nv_bfloat162 h = __floats2bfloat162_rn(x, y);
    hi = *reinterpret_cast<uint32_t*>(&h);
    __nv_bfloat162 l = __floats2bfloat162_rn(x - __bfloat162float(h.x),
                                             y - __bfloat162float(h.y));
    lo = *reinterpret_cast<uint32_t*>(&l);
}

// ===========================================================================
// Pre-split x / w_qkv to bf16 hi/lo
// ===========================================================================
__global__ void __launch_bounds__(256) k_split(const float* __restrict__ src,
                                               __nv_bfloat16* __restrict__ hi,
                                               __nv_bfloat16* __restrict__ lo,
                                               int n4)
{
    int i = blockIdx.x * blockDim.x + threadIdx.x;
    if (i >= n4) return;
    float4 v = reinterpret_cast<const float4*>(src)[i];
    uint32_t h0, l0, h1, l1;
    packhl(v.x, v.y, h0, l0);
    packhl(v.z, v.w, h1, l1);
    reinterpret_cast<uint32_t*>(hi)[i * 2]     = h0;
    reinterpret_cast<uint32_t*>(hi)[i * 2 + 1] = h1;
    reinterpret_cast<uint32_t*>(lo)[i * 2]     = l0;
    reinterpret_cast<uint32_t*>(lo)[i * 2 + 1] = l1;
}

// ===========================================================================
// QKV projection: 128x128 block, split bf16, cp.async double-buffered,
// bf16 V-hi side-copy in epilogue.
// ===========================================================================
#define PSTR 20
#define QKV_STAGE (4 * 128 * PSTR)

__device__ __forceinline__ void qkv_issue(uint32_t base, int row0, int col0,
                                          int k0, int t)
{
    #pragma unroll
    for (int i = 0; i < 2; i++) {
        int idx = t + i * 256;
        int r = idx >> 2, seg = idx & 3;
        uint32_t dst = base + (uint32_t)(r * PSTR + seg * 4) * 4;
        size_t so = (size_t)(row0 + r) * EMB + k0 + seg * 8;
        cp16(dst,                  g_xh + so);
        cp16(dst + 128 * PSTR * 4, g_xl + so);
    }
    #pragma unroll
    for (int i = 0; i < 2; i++) {
        int idx = t + i * 256;
        int r = idx >> 2, seg = idx & 3;
        uint32_t dst = base + (uint32_t)(2 * 128 * PSTR + r * PSTR + seg * 4) * 4;
        size_t so = (size_t)(col0 + r) * EMB + k0 + seg * 8;
        cp16(dst,                  g_wh + so);
        cp16(dst + 128 * PSTR * 4, g_wl + so);
    }
    CP_COMMIT();
}

__global__ void __launch_bounds__(256, 2) k_qkv(const float* __restrict__ bias)
{
    extern __shared__ uint32_t smu[];

    const int row0 = blockIdx.y * 128, col0 = blockIdx.x * 128;
    const int t = threadIdx.x, warp = t >> 5, lane = t & 31;
    const int wm = warp >> 2, wn = warp & 3;
    const int g = lane >> 2, tg = lane & 3;
    const int lr = lane & 15, lc = (lane >> 4) << 2;

    const uint32_t sbase = smaddr(smu);
    float acc[4][4][4] = {};

    qkv_issue(sbase, row0, col0, 0, t);

    for (int s = 0; s < 24; s++) {
        if (s < 23) {
            qkv_issue(sbase + ((s + 1) & 1) * (QKV_STAGE * 4), row0, col0,
                      (s + 1) * 32, t);
            asm volatile("cp.async.wait_group 1;" ::: "memory");
        } else {
            asm volatile("cp.async.wait_group 0;" ::: "memory");
        }
        __syncthreads();

        const uint32_t sb  = sbase + (s & 1) * (QKV_STAGE * 4);
        const uint32_t aAh = sb + (uint32_t)((wm * 64 + lr) * PSTR + lc) * 4;
        const uint32_t aAl = aAh + 128 * PSTR * 4;
        const uint32_t aBh = sb + (uint32_t)(2 * 128 * PSTR + (wn * 32 + lr) * PSTR + lc) * 4;
        const uint32_t aBl = aBh + 128 * PSTR * 4;

        #pragma unroll
        for (int ks = 0; ks < 2; ks++) {
            const uint32_t po = (uint32_t)(ks * 8) * 4;
            uint32_t bh[2][4], bl[2][4];
            #pragma unroll
            for (int j = 0; j < 2; j++) {
                ldsm4(bh[j], aBh + (uint32_t)(j * 16 * PSTR) * 4 + po);
                ldsm4(bl[j], aBl + (uint32_t)(j * 16 * PSTR) * 4 + po);
            }
            #pragma unroll
            for (int mi = 0; mi < 4; mi++) {
                uint32_t ah[4], al[4];
                ldsm4(ah, aAh + (uint32_t)(mi * 16 * PSTR) * 4 + po);
                ldsm4(al, aAl + (uint32_t)(mi * 16 * PSTR) * 4 + po);
                #pragma unroll
                for (int j = 0; j < 2; j++)
                    #pragma unroll
                    for (int ni = 0; ni < 2; ni++) {
                        float* c = acc[mi][j * 2 + ni];
                        mma16(c, ah, bh[j][ni], bh[j][2 + ni]);
                        mma16(c, ah, bl[j][ni], bl[j][2 + ni]);
                        mma16(c, al, bh[j][ni], bh[j][2 + ni]);
                    }
            }
        }
        __syncthreads();
    }

    const bool isV = (col0 >= 2 * EMB);
    #pragma unroll
    for (int mi = 0; mi < 4; mi++) {
        int r0 = row0 + wm * 64 + mi * 16 + g;
        #pragma unroll
        for (int q = 0; q < 4; q++) {
            int c = col0 + wn * 32 + q * 8 + 2 * tg;
            float b0 = bias[c], b1 = bias[c + 1];
            float v00 = acc[mi][q][0] + b0, v01 = acc[mi][q][1] + b1;
            float v10 = acc[mi][q][2] + b0, v11 = acc[mi][q][3] + b1;
            *reinterpret_cast<float2*>(&g_qkv[(size_t)r0       * FQKV + c]) = make_float2(v00, v01);
            *reinterpret_cast<float2*>(&g_qkv[(size_t)(r0 + 8) * FQKV + c]) = make_float2(v10, v11);
            if (isV) {
                int cv = c - 2 * EMB;
                *reinterpret_cast<__nv_bfloat162*>(&g_vh[(size_t)r0       * EMB + cv]) =
                    __floats2bfloat162_rn(v00, v01);
                *reinterpret_cast<__nv_bfloat162*>(&g_vh[(size_t)(r0 + 8) * EMB + cv]) =
                    __floats2bfloat162_rn(v10, v11);
            }
        }
    }
}

// ===========================================================================
// Output projection: tf32, 128x128 tile (R13 version)
// ===========================================================================
__global__ void __launch_bounds__(256) k_out(const float* __restrict__ w,
                                             const float* __restrict__ bias,
                                             float* __restrict__ out)
{
    extern __shared__ uint32_t smo[];
    uint32_t* Ah = smo;
    uint32_t* Bh = Ah + 128 * 36;

    const int row0 = blockIdx.y * 128, col0 = blockIdx.x * 128;
    const int t = threadIdx.x, warp = t >> 5, lane = t & 31;
    const int wm = warp >> 2, wn = warp & 3;
    const int g = lane >> 2, tg = lane & 3;
    const int lr = lane & 15, lc = (lane >> 4) << 2;

    const uint32_t aA = smaddr(Ah) + (uint32_t)((wm * 64 + lr) * 36 + lc) * 4;
    const uint32_t aB = smaddr(Bh) + (uint32_t)((wn * 32 + lr) * 36 + lc) * 4;

    float acc[4][4][4] = {};
    float4 pa[4], pb[4];

    #pragma unroll
    for (int i = 0; i < 4; i++) {
        int idx = t + i * 256;
        int r = idx >> 3, c4 = (idx & 7) * 4;
        pa[i] = *reinterpret_cast<const float4*>(&g_oh[(size_t)(row0 + r) * EMB + c4]);
        pb[i] = *reinterpret_cast<const float4*>(&w[(size_t)(col0 + r) * EMB + c4]);
    }

    for (int k0 = 0; k0 < EMB; k0 += 32) {
        __syncthreads();
        #pragma unroll
        for (int i = 0; i < 4; i++) {
            int idx = t + i * 256;
            int r = idx >> 3, c4 = (idx & 7) * 4;
            Ah[r * 36 + c4 + 0] = f2tf(pa[i].x); Ah[r * 36 + c4 + 1] = f2tf(pa[i].y);
            Ah[r * 36 + c4 + 2] = f2tf(pa[i].z); Ah[r * 36 + c4 + 3] = f2tf(pa[i].w);
            Bh[r * 36 + c4 + 0] = f2tf(pb[i].x); Bh[r * 36 + c4 + 1] = f2tf(pb[i].y);
            Bh[r * 36 + c4 + 2] = f2tf(pb[i].z); Bh[r * 36 + c4 + 3] = f2tf(pb[i].w);
        }
        __syncthreads();

        int kn = k0 + 32;
        if (kn < EMB) {
            #pragma unroll
            for (int i = 0; i < 4; i++) {
                int idx = t + i * 256;
                int r = idx >> 3, c4 = (idx & 7) * 4;
                pa[i] = *reinterpret_cast<const float4*>(&g_oh[(size_t)(row0 + r) * EMB + kn + c4]);
                pb[i] = *reinterpret_cast<const float4*>(&w[(size_t)(col0 + r) * EMB + kn + c4]);
            }
        }

        #pragma unroll
        for (int ks = 0; ks < 4; ks++) {
            const uint32_t ko = (uint32_t)(ks * 8) * 4;
            uint32_t a[4][4], b[2][4];
            ldsm4(b[0], aB + ko);
            ldsm4(b[1], aB + (uint32_t)(16 * 36) * 4 + ko);
            #pragma unroll
            for (int mi = 0; mi < 4; mi++)
                ldsm4(a[mi], aA + (uint32_t)(mi * 16 * 36) * 4 + ko);
            #pragma unroll
            for (int mi = 0; mi < 4; mi++)
                #pragma unroll
                for (int j = 0; j < 2; j++)
                    #pragma unroll
                    for (int ni = 0; ni < 2; ni++)
                        mma8(acc[mi][j * 2 + ni], a[mi][0], a[mi][1], a[mi][2], a[mi][3],
                             b[j][ni], b[j][2 + ni]);
        }
    }

    #pragma unroll
    for (int mi = 0; mi < 4; mi++) {
        int r0 = row0 + wm * 64 + mi * 16 + g;
        #pragma unroll
        for (int q = 0; q < 4; q++) {
            int c = col0 + wn * 32 + q * 8 + 2 * tg;
            float b0 = bias[c], b1 = bias[c + 1];
            *reinterpret_cast<float2*>(&out[(size_t)r0       * EMB + c]) =
                make_float2(acc[mi][q][0] + b0, acc[mi][q][1] + b1);
            *reinterpret_cast<float2*>(&out[(size_t)(r0 + 8) * EMB + c]) =
                make_float2(acc[mi][q][2] + b0, acc[mi][q][3] + b1);
        }
    }
}

// ===========================================================================
// Fused attention v5: register-resident S, log2-domain softmax, PV with
// split-P x V-hi (2 mma16) and x4.trans V fragment loads.
// ===========================================================================
#define RT2   32
#define KST2  68
#define VST2  72
#define KBUF  (128 * KST2)          // floats per K buffer
#define VBUF  (128 * VST2)          // bf16 per V buffer (ring4 aliases K region)
#define SMO_MSC  139264             // after K ring4 (4*34816)
#define SMO_FSC  (SMO_MSC + 2048)
#define SMB_ATTN (SMO_FSC + 256)    // 141568 B

__device__ __forceinline__ void a_issue_k(char* smc, const float* __restrict__ Kg,
                                          int s, int t)
{
    float* kb = (float*)smc + (size_t)(s & 3) * KBUF;
    #pragma unroll
    for (int i = 0; i < 4; i++) {
        int idx = t + i * 512;
        int r = idx >> 4, c4 = (idx & 15) * 4;
        cp16(smaddr(kb + r * KST2 + c4), Kg + (size_t)(s * 128 + r) * FQKV + c4);
    }
    CP_COMMIT();
}

__device__ __forceinline__ void a_issue_v(char* smc,
                                          const __nv_bfloat16* __restrict__ VgH,
                                          int s, int t)
{
    __nv_bfloat16* vh = (__nv_bfloat16*)smc + (size_t)(s & 3) * VBUF;
    #pragma unroll
    for (int i = 0; i < 2; i++) {
        int idx = t + i * 512;
        int r = idx >> 3, seg = idx & 7;
        cp16(smaddr(vh + r * VST2 + seg * 8),
             VgH + (size_t)(s * 128 + r) * EMB + seg * 8);
    }
    CP_COMMIT();
}

__global__ void __launch_bounds__(512) k_attn(float* __restrict__ attn)
{
    extern __shared__ char smc[];
    float* mscr = (float*)(smc + SMO_MSC);
    float* fscr = (float*)(smc + SMO_FSC);

    const int bh = blockIdx.y;
    const int bb = bh / NHEAD, h = bh % NHEAD;
    const int row0 = blockIdx.x * RT2;
    const int t = threadIdx.x, warp = t >> 5, lane = t & 31;
    const int g = lane >> 2, tg = lane & 3;
    const int wm = warp >> 3;
    const int wn = warp & 7;
    const int lr = lane & 15, lc = (lane >> 4) << 2;

    const float* Qg = g_qkv + ((size_t)bb * SEQ + row0) * FQKV + h * HDIM;
    const float* Kg = g_qkv + (size_t)bb * SEQ * FQKV + EMB + h * HDIM;
    const __nv_bfloat16* VgH = g_vh + (size_t)bb * SEQ * EMB + h * HDIM;

    {
        float* Kb = (float*)smc;
        int r = t >> 4, c4 = (t & 15) * 4;
        float4 v = *reinterpret_cast<const float4*>(&Qg[(size_t)r * FQKV + c4]);
        Kb[r * KST2 + c4 + 0] = v.x; Kb[r * KST2 + c4 + 1] = v.y;
        Kb[r * KST2 + c4 + 2] = v.z; Kb[r * KST2 + c4 + 3] = v.w;
    }
    __syncthreads();
    uint32_t qf[8][4];
    {
        const float* Kb = (const float*)smc;
        const int rb = wm * 16;
        #pragma unroll
        for (int ks = 0; ks < 8; ks++) {
            int kb = ks * 8;
            qf[ks][0] = f2tf(Kb[(rb + g    ) * KST2 + kb + tg]);
            qf[ks][1] = f2tf(Kb[(rb + g + 8) * KST2 + kb + tg]);
            qf[ks][2] = f2tf(Kb[(rb + g    ) * KST2 + kb + tg + 4]);
            qf[ks][3] = f2tf(Kb[(rb + g + 8) * KST2 + kb + tg + 4]);
        }
    }
    __syncthreads();

    const uint32_t kfrag = (uint32_t)((wn * 16 + lr) * KST2 + lc) * 4;
    const float sc2 = 0.125f * 1.4426950408889634f;   // log2 domain

    a_issue_k(smc, Kg, 0, t);
    a_issue_k(smc, Kg, 1, t);

    float Sreg[8][2][4];

    for (int s = 0; s < 8; s++) {
        if (s < 6) {
            a_issue_k(smc, Kg, s + 2, t);
            asm volatile("cp.async.wait_group 2;" ::: "memory");
        } else if (s == 6) {
            asm volatile("cp.async.wait_group 1;" ::: "memory");
        } else {
            asm volatile("cp.async.wait_group 0;" ::: "memory");
        }
        __syncthreads();
        const uint32_t kbase = smaddr((float*)smc + (size_t)(s & 3) * KBUF) + kfrag;

        float acc[2][4] = {};
        #pragma unroll
        for (int ks = 0; ks < 8; ks++) {
            uint32_t b[4];
            ldsm4(b, kbase + (uint32_t)(ks * 8) * 4);
            mma8(acc[0], qf[ks][0], qf[ks][1], qf[ks][2], qf[ks][3], b[0], b[2]);
            mma8(acc[1], qf[ks][0], qf[ks][1], qf[ks][2], qf[ks][3], b[1], b[3]);
        }
        #pragma unroll
        for (int ni = 0; ni < 2; ni++)
            #pragma unroll
            for (int v = 0; v < 4; v++)
                Sreg[s][ni][v] = acc[ni][v] * sc2;
    }

    float mA = -1e30f, mB = -1e30f;
    #pragma unroll
    for (int s = 0; s < 8; s++)
        #pragma unroll
        for (int ni = 0; ni < 2; ni++) {
            mA = fmaxf(mA, fmaxf(Sreg[s][ni][0], Sreg[s][ni][1]));
            mB = fmaxf(mB, fmaxf(Sreg[s][ni][2], Sreg[s][ni][3]));
        }
    float lA = 0.0f, lB = 0.0f;
    #pragma unroll
    for (int s = 0; s < 8; s++)
        #pragma unroll
        for (int ni = 0; ni < 2; ni++) {
            lA += ex2f(Sreg[s][ni][0] - mA) + ex2f(Sreg[s][ni][1] - mA);
            lB += ex2f(Sreg[s][ni][2] - mB) + ex2f(Sreg[s][ni][3] - mB);
        }
    #pragma unroll
    for (int off = 1; off <= 2; off <<= 1) {
        float mo = __shfl_xor_sync(0xffffffffu, mA, off);
        float lo = __shfl_xor_sync(0xffffffffu, lA, off);
        float mn = fmaxf(mA, mo);
        lA = lA * ex2f(mA - mn) + lo * ex2f(mo - mn); mA = mn;
        mo = __shfl_xor_sync(0xffffffffu, mB, off);
        lo = __shfl_xor_sync(0xffffffffu, lB, off);
        mn = fmaxf(mB, mo);
        lB = lB * ex2f(mB - mn) + lo * ex2f(mo - mn); mB = mn;
    }

    a_issue_v(smc, VgH, 0, t);

    if (tg == 0) {
        mscr[(wn * 32 + wm * 16 + g    ) * 2]     = mA;
        mscr[(wn * 32 + wm * 16 + g    ) * 2 + 1] = lA;
        mscr[(wn * 32 + wm * 16 + g + 8) * 2]     = mB;
        mscr[(wn * 32 + wm * 16 + g + 8) * 2 + 1] = lB;
    }
    __syncthreads();

    a_issue_v(smc, VgH, 1, t);

    if (t < 32) {
        float M = -1e30f, L = 0.0f;
        #pragma unroll
        for (int j = 0; j < 8; j++) {
            float mj = mscr[(j * 32 + t) * 2];
            float lj = mscr[(j * 32 + t) * 2 + 1];
            float mn = fmaxf(M, mj);
            L = L * ex2f(M - mn) + lj * ex2f(mj - mn);
            M = mn;
        }
        fscr[t * 2]     = M;
        fscr[t * 2 + 1] = 1.0f / L;
    }
    __syncthreads();
    const float mf0 = fscr[(wm * 16 + g    ) * 2];
    const float iv0 = fscr[(wm * 16 + g    ) * 2 + 1];
    const float mf1 = fscr[(wm * 16 + g + 8) * 2];
    const float iv1 = fscr[(wm * 16 + g + 8) * 2 + 1];

    float O[8][4] = {};
    float* ar0 = attn + ((size_t)bh * SEQ + row0 + wm * 16 + g) * SEQ;
    float* ar1 = ar0 + 8 * SEQ;

    for (int s = 0; s < 8; s++) {
        if (s < 6) {
            a_issue_v(smc, VgH, s + 2, t);
            asm volatile("cp.async.wait_group 2;" ::: "memory");
        } else if (s == 6) {
            asm volatile("cp.async.wait_group 1;" ::: "memory");
        } else {
            asm volatile("cp.async.wait_group 0;" ::: "memory");
        }
        __syncthreads();

        float p00 = ex2f(Sreg[s][0][0] - mf0) * iv0;
        float p01 = ex2f(Sreg[s][0][1] - mf0) * iv0;
        float p02 = ex2f(Sreg[s][1][0] - mf0) * iv0;
        float p03 = ex2f(Sreg[s][1][1] - mf0) * iv0;
        float q00 = ex2f(Sreg[s][0][2] - mf1) * iv1;
        float q01 = ex2f(Sreg[s][0][3] - mf1) * iv1;
        float q02 = ex2f(Sreg[s][1][2] - mf1) * iv1;
        float q03 = ex2f(Sreg[s][1][3] - mf1) * iv1;

        int c = s * 128 + wn * 16 + 2 * tg;
        *reinterpret_cast<float2*>(&ar0[c])     = make_float2(p00, p01);
        *reinterpret_cast<float2*>(&ar0[c + 8]) = make_float2(p02, p03);
        *reinterpret_cast<float2*>(&ar1[c])     = make_float2(q00, q01);
        *reinterpret_cast<float2*>(&ar1[c + 8]) = make_float2(q02, q03);

        uint32_t ah[4], al[4];
        packhl(p00, p01, ah[0], al[0]);
        packhl(q00, q01, ah[1], al[1]);
        packhl(p02, p03, ah[2], al[2]);
        packhl(q02, q03, ah[3], al[3]);

        // V fragments via x4.trans: lanes 16-31 take the +8-column tile
        const uint32_t vbase = smaddr((const __nv_bfloat16*)smc +
                                      (size_t)(s & 3) * VBUF +
                                      (wn * 16 + lr) * VST2 + (lane >> 4) * 8);
        #pragma unroll
        for (int nt2 = 0; nt2 < 4; nt2++) {
            uint32_t b[4];
            ldsm4t(b, vbase + (uint32_t)(nt2 * 16) * 2);
            mma16(O[2 * nt2],     ah, b[0], b[1]);
            mma16(O[2 * nt2],     al, b[0], b[1]);
            mma16(O[2 * nt2 + 1], ah, b[2], b[3]);
            mma16(O[2 * nt2 + 1], al, b[2], b[3]);
        }
    }

    __syncthreads();
    float* R = (float*)smc;
    if (wn > 0) {
        float* Rp = R + (size_t)((wn - 1) * 2 + wm) * 1024;
        #pragma unroll
        for (int nt = 0; nt < 8; nt++) {
            *reinterpret_cast<float2*>(&Rp[(g    ) * 64 + nt * 8 + 2 * tg]) =
                make_float2(O[nt][0], O[nt][1]);
            *reinterpret_cast<float2*>(&Rp[(g + 8) * 64 + nt * 8 + 2 * tg]) =
                make_float2(O[nt][2], O[nt][3]);
        }
    }
    __syncthreads();
    if (wn == 0) {
        #pragma unroll
        for (int j = 0; j < 7; j++) {
            const float* Rp = R + (size_t)(j * 2 + wm) * 1024;
            #pragma unroll
            for (int nt = 0; nt < 8; nt++) {
                float2 a0 = *reinterpret_cast<const float2*>(&Rp[(g    ) * 64 + nt * 8 + 2 * tg]);
                float2 a1 = *reinterpret_cast<const float2*>(&Rp[(g + 8) * 64 + nt * 8 + 2 * tg]);
                O[nt][0] += a0.x; O[nt][1] += a0.y;
                O[nt][2] += a1.x; O[nt][3] += a1.y;
            }
        }
        float* o0 = g_oh + ((size_t)bb * SEQ + row0 + wm * 16 + g) * EMB + h * HDIM;
        float* o1 = o0 + 8 * EMB;
        #pragma unroll
        for (int nt = 0; nt < 8; nt++) {
            *reinterpret_cast<float2*>(&o0[nt * 8 + 2 * tg]) = make_float2(O[nt][0], O[nt][1]);
            *reinterpret_cast<float2*>(&o1[nt * 8 + 2 * tg]) = make_float2(O[nt][2], O[nt][3]);
        }
    }
}

// ---------------------------------------------------------------------------
extern "C" void kernel_launch(void* const* d_in, const int* in_sizes, int n_in,
                              void* d_out, int out_size)
{
    const float* x     = (const float*)d_in[0];
    const float* w_qkv = (const float*)d_in[1];
    const float* b_qkv = (const float*)d_in[2];
    const float* w_out = (const float*)d_in[3];
    const float* b_out = (const float*)d_in[4];

    float* out  = (float*)d_out;
    float* attn = out + (size_t)MTOT * EMB;

    const int smem_qkv  = 2 * QKV_STAGE * 4;          // 81920
    const int smem_out  = (128 * 36 + 128 * 36) * 4;  // 36864
    const int smem_attn = SMB_ATTN;                   // 141568

    static bool attr_done = false;
    if (!attr_done) {
        cudaFuncSetAttribute(k_qkv,  cudaFuncAttributeMaxDynamicSharedMemorySize, smem_qkv);
        cudaFuncSetAttribute(k_out,  cudaFuncAttributeMaxDynamicSharedMemorySize, smem_out);
        cudaFuncSetAttribute(k_attn, cudaFuncAttributeMaxDynamicSharedMemorySize, smem_attn);
        attr_done = true;
    }

    __nv_bfloat16 *xh, *xl, *wh, *wl;
    cudaGetSymbolAddress((void**)&xh, g_xh);
    cudaGetSymbolAddress((void**)&xl, g_xl);
    cudaGetSymbolAddress((void**)&wh, g_wh);
    cudaGetSymbolAddress((void**)&wl, g_wl);

    const int nx4 = MTOT * EMB / 4;
    const int nw4 = FQKV * EMB / 4;

    k_split<<<(nx4 + 255) / 256, 256>>>(x,     xh, xl, nx4);
    k_split<<<(nw4 + 255) / 256, 256>>>(w_qkv, wh, wl, nw4);

    k_qkv <<<dim3(FQKV / 128, MTOT / 128), 256, smem_qkv >>>(b_qkv);
    k_attn<<<dim3(SEQ / RT2, BHTOT),       512, smem_attn>>>(attn);
    k_out <<<dim3(EMB / 128, MTOT / 128),  256, smem_out >>>(w_out, b_out, out);
}